// round 12
// baseline (speedup 1.0000x reference)
#include <cuda_runtime.h>
#include <cuda_fp16.h>
#include <math.h>
#include <stdint.h>

#define TOKENS 4096
#define DM     1024
#define DFF    4096
#define SEQ    2048
#define NH     16
#define DK     64

// ---------------- scratch ----------------
__device__ float g_x1[TOKENS*DM];
__device__ float g_cs[SEQ*32];
__device__ float g_sn[SEQ*32];

__device__ __half g_h1[TOKENS*DM];
__device__ __half g_at[TOKENS*DM];
__device__ __half g_h2[TOKENS*DM];
__device__ __half g_gb[TOKENS*DFF];
__device__ __half g_q[TOKENS*DM];
__device__ __half g_k[TOKENS*DM];
__device__ __half g_v[TOKENS*DM];

#define WOFF_Q  0
#define WOFF_K  (1u<<20)
#define WOFF_V  (2u<<20)
#define WOFF_O  (3u<<20)
#define WOFF_1  (4u<<20)
#define WOFF_3  (8u<<20)
#define WOFF_2  (12u<<20)
__device__ __half g_w[16u<<20];

// ---------------- helpers ----------------
__device__ __forceinline__ uint32_t smem_u32(const void* p){
    uint32_t r;
    asm("{ .reg .u64 t; cvta.to.shared.u64 t, %1; cvt.u32.u64 %0, t; }" : "=r"(r) : "l"(p));
    return r;
}
__device__ __forceinline__ void cpa16(uint32_t dst, const void* src){
    asm volatile("cp.async.cg.shared.global [%0], [%1], 16;" :: "r"(dst), "l"(src) : "memory");
}
__device__ __forceinline__ void cp_commit(){ asm volatile("cp.async.commit_group;" ::: "memory"); }
__device__ __forceinline__ void cp_wait2(){ asm volatile("cp.async.wait_group 2;" ::: "memory"); }
__device__ __forceinline__ void cp_wait1(){ asm volatile("cp.async.wait_group 1;" ::: "memory"); }
__device__ __forceinline__ void cp_wait0(){ asm volatile("cp.async.wait_group 0;" ::: "memory"); }

__device__ __forceinline__ void ldsm4(uint32_t* r, uint32_t addr){
    asm volatile("ldmatrix.sync.aligned.m8n8.x4.shared.b16 {%0,%1,%2,%3}, [%4];"
        : "=r"(r[0]),"=r"(r[1]),"=r"(r[2]),"=r"(r[3]) : "r"(addr));
}
__device__ __forceinline__ void ldsm4t(uint32_t* r, uint32_t addr){
    asm volatile("ldmatrix.sync.aligned.m8n8.x4.trans.shared.b16 {%0,%1,%2,%3}, [%4];"
        : "=r"(r[0]),"=r"(r[1]),"=r"(r[2]),"=r"(r[3]) : "r"(addr));
}
__device__ __forceinline__ void mma16816(float* c, const uint32_t* a, uint32_t b0, uint32_t b1){
    asm volatile("mma.sync.aligned.m16n8k16.row.col.f32.f16.f16.f32 "
        "{%0,%1,%2,%3}, {%4,%5,%6,%7}, {%8,%9}, {%0,%1,%2,%3};"
        : "+f"(c[0]),"+f"(c[1]),"+f"(c[2]),"+f"(c[3])
        : "r"(a[0]),"r"(a[1]),"r"(a[2]),"r"(a[3]), "r"(b0),"r"(b1));
}
#define SW128(o) ((o) ^ (((o)>>3)&0x70))

__device__ __forceinline__ uint32_t f22h(float x, float y){
    __half2 h = __floats2half2_rn(x, y);
    return *reinterpret_cast<uint32_t*>(&h);
}

// ---------------- RoPE table ----------------
__global__ void rope_table_k() {
    __shared__ float invf[32];
    int t = threadIdx.x;
    if (t < 32) invf[t] = (float)pow(10000.0, -(double)(2 * t) / 64.0);
    __syncthreads();
    int i = blockIdx.x * 256 + t;
    int pos = i >> 5;
    int j   = i & 31;
    float ang = (float)pos * invf[j];
    g_cs[i] = cosf(ang);
    g_sn[i] = sinf(ang);
}

// ---------------- all weight conversions fp32 -> fp16 ----------------
__global__ void cvt_all_k(const float* __restrict__ Wq, const float* __restrict__ Wk,
                          const float* __restrict__ Wv, const float* __restrict__ Wo,
                          const float* __restrict__ W1, const float* __restrict__ W3,
                          const float* __restrict__ W2, __half* __restrict__ w){
    int gb = blockIdx.x;
    const float* src; uint32_t woff; int lb;
    if (gb < 1024){
        int m = gb >> 8; lb = gb & 255;
        src = (m==0)?Wq:(m==1)?Wk:(m==2)?Wv:Wo;
        woff = (uint32_t)m << 20;
    } else if (gb < 2048){ src = W1; woff = WOFF_1; lb = gb - 1024; }
    else if (gb < 3072){ src = W3; woff = WOFF_3; lb = gb - 2048; }
    else               { src = W2; woff = WOFF_2; lb = gb - 3072; }
    uint2* hp = (uint2*)(w + woff);
    #pragma unroll
    for (int j = 0; j < 4; j++){
        int i4 = lb * 1024 + j * 256 + threadIdx.x;
        float4 v = ((const float4*)src)[i4];
        hp[i4] = make_uint2(f22h(v.x, v.y), f22h(v.z, v.w));
    }
}

// ---------------- RMSNorm -> fp16 ----------------
__global__ __launch_bounds__(256) void rms_h_k(const float* __restrict__ x,
                                               const float* __restrict__ g,
                                               __half* __restrict__ o) {
    int row = blockIdx.x;
    int t   = threadIdx.x;
    const float4* xr = (const float4*)(x + (size_t)row * DM);
    float4 xv = xr[t];
    float ss = xv.x*xv.x + xv.y*xv.y + xv.z*xv.z + xv.w*xv.w;
    #pragma unroll
    for (int off = 16; off > 0; off >>= 1)
        ss += __shfl_xor_sync(0xffffffffu, ss, off);
    __shared__ float warpsum[8];
    if ((t & 31) == 0) warpsum[t >> 5] = ss;
    __syncthreads();
    float tot = warpsum[0]+warpsum[1]+warpsum[2]+warpsum[3]
              + warpsum[4]+warpsum[5]+warpsum[6]+warpsum[7];
    float r = rsqrtf(tot * (1.0f / (float)DM) + 1e-5f);
    float4 gv = ((const float4*)g)[t];
    size_t base4 = (size_t)row * (DM/4) + t;
    ((uint2*)o)[base4] = make_uint2(f22h(xv.x*r*gv.x, xv.y*r*gv.y),
                                    f22h(xv.z*r*gv.z, xv.w*r*gv.w));
}

// =====================================================================
// fp16 GEMM engine: CTA 128x128, 256 thr (8 warps, 2x4 of 64x32),
// BK=64, SW128 128B rows, 3-stage. Stage (32 KB): A@0(16K) B@16K(16K).
// MMA:LDSM = 2.67. launch_bounds(256,2) -> 2 CTAs/SM.
// =====================================================================
#define STG64X   32768
#define G64_SMEM (3*STG64X)

__device__ __forceinline__ void g64_load(
    uint32_t tb, int tid, int m0, int n0, int kc, int K,
    const __half* A, const __half* B)
{
    int k0 = kc * 64;
    #pragma unroll
    for (int j = 0; j < 4; j++){
        int i = j * 256 + tid;     // 1024 chunks: A rows 0..127
        int r = i >> 3, c16 = i & 7;
        cpa16(tb + SW128((uint32_t)(r << 7) + (c16 << 4)),
              A + (size_t)(m0 + r) * K + k0 + c16 * 8);
    }
    #pragma unroll
    for (int j = 0; j < 4; j++){
        int i = j * 256 + tid;     // 1024 chunks: B rows 0..127
        int r = i >> 3, c16 = i & 7;
        cpa16(tb + 16384 + SW128((uint32_t)(r << 7) + (c16 << 4)),
              B + (size_t)(n0 + r) * K + k0 + c16 * 8);
    }
    cp_commit();
}

// one BK=64 chunk, warp tile 64x32, acc[4][4][4]
__device__ __forceinline__ void g64_chunk(
    uint32_t tb, int lane, int wm, int wn, float acc[4][4][4])
{
    #pragma unroll
    for (int s = 0; s < 4; s++){
        uint32_t colb = (uint32_t)(s*32) + ((lane >> 4) << 4);
        uint32_t a[4][4], b[2][4];
        #pragma unroll
        for (int t = 0; t < 4; t++)
            ldsm4(a[t], tb + SW128((uint32_t)((wm*64 + t*16 + (lane & 15)) << 7) + colb));
        #pragma unroll
        for (int g = 0; g < 2; g++)
            ldsm4(b[g], tb + 16384 + SW128((uint32_t)((wn*32 + g*16 + (lane & 15)) << 7) + colb));
        #pragma unroll
        for (int t = 0; t < 4; t++)
            #pragma unroll
            for (int g = 0; g < 2; g++)
                #pragma unroll
                for (int j = 0; j < 2; j++)
                    mma16816(acc[t][g*2+j], a[t], b[g][j], b[g][j+2]);
    }
}

#define G64_MAIN(A_, B_, KDIM)                                                \
    g64_load(sb, tid, m0, n0, 0, KDIM, A_, B_);                               \
    g64_load(sb + STG64X, tid, m0, n0, 1, KDIM, A_, B_);                      \
    for (int kc = 0; kc < NC; kc++){                                          \
        if (kc + 1 < NC) cp_wait1(); else cp_wait0();                         \
        __syncthreads();                                                      \
        if (kc + 2 < NC)                                                      \
            g64_load(sb + ((kc+2)%3)*STG64X, tid, m0, n0, kc+2, KDIM, A_, B_);\
        g64_chunk(sb + (kc%3)*STG64X, lane, wm, wn, acc);                     \
    }

// ---------------- fused QKV GEMM (N=3072) ----------------
__global__ __launch_bounds__(256, 2) void gemm_qkv(
    const __half* __restrict__ A, const __half* __restrict__ B,
    __half* __restrict__ Q, __half* __restrict__ K_, __half* __restrict__ V)
{
    extern __shared__ char smem[];
    uint32_t sb = smem_u32(smem);
    const int tid  = threadIdx.x;
    const int lane = tid & 31;
    const int wid  = tid >> 5;
    const int wm   = wid & 1;       // 2 row groups of 64
    const int wn   = wid >> 1;      // 4 col groups of 32
    const int m0 = blockIdx.y * 128, n0 = blockIdx.x * 128;
    const int NC = DM / 64;

    float acc[4][4][4];
    #pragma unroll
    for (int i = 0; i < 4; i++)
        #pragma unroll
        for (int j = 0; j < 4; j++)
            #pragma unroll
            for (int kk = 0; kk < 4; kk++) acc[i][j][kk] = 0.0f;

    G64_MAIN(A, B, DM)

    const int mtx = n0 >> 10;
    const float scl = (mtx == 0) ? 0.125f : 1.0f;
    __half* D = (mtx==0)?Q:(mtx==1)?K_:V;
    const int gid = lane >> 2, tig = lane & 3;
    #pragma unroll
    for (int tm = 0; tm < 4; tm++){
        #pragma unroll
        for (int half = 0; half < 2; half++){
            int m = m0 + wm*64 + tm*16 + gid + half*8;
            int pos = m & (SEQ - 1), b = m >> 11;
            #pragma unroll
            for (int tn = 0; tn < 4; tn++){
                int cc = (n0 & 1023) + wn*32 + tn*8 + tig*2;
                int head = cc >> 6, hi = cc & 63;
                size_t ob = ((size_t)(b * NH + head) * SEQ + pos) * DK + hi;
                float v0 = acc[tm][tn][half*2];
                float v1 = acc[tm][tn][half*2 + 1];
                float w0, w1;
                if (mtx < 2){
                    float cs = g_cs[pos * 32 + (hi >> 1)];
                    float sn = g_sn[pos * 32 + (hi >> 1)];
                    w0 = (v0 * cs - v1 * sn) * scl;
                    w1 = (v0 * sn + v1 * cs) * scl;
                } else { w0 = v0; w1 = v1; }
                *(uint32_t*)(D + ob) = f22h(w0, w1);
            }
        }
    }
}

// ---------------- GEMM + residual add (Wo, W2) ----------------
__global__ __launch_bounds__(256, 2) void gemm_add(
    const __half* __restrict__ A, const __half* __restrict__ B,
    float* __restrict__ C, const float* __restrict__ other, int N, int K)
{
    extern __shared__ char smem[];
    uint32_t sb = smem_u32(smem);
    const int tid  = threadIdx.x;
    const int lane = tid & 31;
    const int wid  = tid >> 5;
    const int wm   = wid & 1;
    const int wn   = wid >> 1;
    const int m0 = blockIdx.y * 128, n0 = blockIdx.x * 128;
    const int NC = K / 64;

    float acc[4][4][4];
    #pragma unroll
    for (int i = 0; i < 4; i++)
        #pragma unroll
        for (int j = 0; j < 4; j++)
            #pragma unroll
            for (int kk = 0; kk < 4; kk++) acc[i][j][kk] = 0.0f;

    G64_MAIN(A, B, K)

    const int gid = lane >> 2, tig = lane & 3;
    #pragma unroll
    for (int tm = 0; tm < 4; tm++){
        #pragma unroll
        for (int half = 0; half < 2; half++){
            int m = m0 + wm*64 + tm*16 + gid + half*8;
            #pragma unroll
            for (int tn = 0; tn < 4; tn++){
                int c = n0 + wn*32 + tn*8 + tig*2;
                size_t base = (size_t)m * N + c;
                C[base]     = other[base] + acc[tm][tn][half*2];
                C[base + 1] = other[base + 1] + acc[tm][tn][half*2 + 1];
            }
        }
    }
}

// ---------------- fused W1/W3 GEMM + silu(u)*v -> fp16 ----------------
// CTA 128x64, 256 thr (8 warps, 2x4 of 64x16 per matrix), dual acc.
// Stage (32 KB): A@0(16K) B1@16K(8K) B3@24K(8K). 3 stages, 2 CTAs/SM.
#define W13_STG   32768
#define W13_SMEM  (3*W13_STG)

__global__ __launch_bounds__(256, 2) void gemm_w13(
    const __half* __restrict__ A,
    const __half* __restrict__ B1, const __half* __restrict__ B3,
    __half* __restrict__ Cg)
{
    extern __shared__ char smem[];
    uint32_t sb = smem_u32(smem);
    const int tid  = threadIdx.x;
    const int lane = tid & 31;
    const int wid  = tid >> 5;
    const int wm   = wid & 1;       // 2 row groups of 64
    const int wn   = wid >> 1;      // 4 col groups of 16
    const int m0 = blockIdx.y * 128, n0 = blockIdx.x * 64;
    const int NC = DM / 64;
    const int K  = DM;

    float accU[4][2][4], accV[4][2][4];
    #pragma unroll
    for (int i = 0; i < 4; i++)
        #pragma unroll
        for (int j = 0; j < 2; j++)
            #pragma unroll
            for (int kk = 0; kk < 4; kk++){ accU[i][j][kk] = 0.0f; accV[i][j][kk] = 0.0f; }

    auto load_chunk = [&](int kc, int stage){
        uint32_t tb = sb + stage * W13_STG;
        int k0 = kc * 64;
        #pragma unroll
        for (int j = 0; j < 4; j++){
            int i = j * 256 + tid;
            int r = i >> 3, c16 = i & 7;
            cpa16(tb + SW128((uint32_t)(r << 7) + (c16 << 4)),
                  A + (size_t)(m0 + r) * K + k0 + c16 * 8);
        }
        #pragma unroll
        for (int j = 0; j < 2; j++){
            int i = j * 256 + tid;
            int r = i >> 3, c16 = i & 7;
            uint32_t o = SW128((uint32_t)(r << 7) + (c16 << 4));
            cpa16(tb + 16384 + o, B1 + (size_t)(n0 + r) * K + k0 + c16 * 8);
            cpa16(tb + 24576 + o, B3 + (size_t)(n0 + r) * K + k0 + c16 * 8);
        }
        cp_commit();
    };

    load_chunk(0, 0);
    load_chunk(1, 1);

    for (int kc = 0; kc < NC; kc++){
        if (kc + 1 < NC) cp_wait1(); else cp_wait0();
        __syncthreads();
        if (kc + 2 < NC) load_chunk(kc + 2, (kc + 2) % 3);
        uint32_t tb = sb + (kc % 3) * W13_STG;

        #pragma unroll
        for (int s = 0; s < 4; s++){
            uint32_t colb = (uint32_t)(s*32) + ((lane >> 4) << 4);
            uint32_t a[4][4], b1[4], b3[4];
            #pragma unroll
            for (int t = 0; t < 4; t++)
                ldsm4(a[t], tb + SW128((uint32_t)((wm*64 + t*16 + (lane & 15)) << 7) + colb));
            {
                uint32_t so = SW128((uint32_t)((wn*16 + (lane & 15)) << 7) + colb);
                ldsm4(b1, tb + 16384 + so);
                ldsm4(b3, tb + 24576 + so);
            }
            #pragma unroll
            for (int t = 0; t < 4; t++)
                #pragma unroll
                for (int j = 0; j < 2; j++){
                    mma16816(accU[t][j], a[t], b1[j], b1[j+2]);
                    mma16816(accV[t][j], a[t], b3[j], b3[j+2]);
                }
        }
    }

    const int gid = lane >> 2, tig = lane & 3;
    #pragma unroll
    for (int tm = 0; tm < 4; tm++){
        #pragma unroll
        for (int half = 0; half < 2; half++){
            int m = m0 + wm*64 + tm*16 + gid + half*8;
            #pragma unroll
            for (int tn = 0; tn < 2; tn++){
                int c = n0 + wn*16 + tn*8 + tig*2;
                size_t base = (size_t)m * DFF + c;
                float u0 = accU[tm][tn][half*2], u1 = accU[tm][tn][half*2+1];
                float v0 = accV[tm][tn][half*2], v1 = accV[tm][tn][half*2+1];
                float w0 = v0 * u0 / (1.0f + __expf(-u0));
                float w1 = v1 * u1 / (1.0f + __expf(-u1));
                *(uint32_t*)(Cg + base) = f22h(w0, w1);
            }
        }
    }
}

// ---------------- fp16 flash attention (causal) ----------------
#define FA_SMEM (16384 + 3*16384)

__global__ __launch_bounds__(256, 2) void flash_tc(
    const __half* __restrict__ Qg, const __half* __restrict__ Kg,
    const __half* __restrict__ Vg, __half* __restrict__ Og)
{
    extern __shared__ char smem[];
    uint32_t sb = smem_u32(smem);
    const int tid  = threadIdx.x;
    const int lane = tid & 31;
    const int w    = tid >> 5;
    const int gid  = lane >> 2, tig = lane & 3;
    const int qt   = (int)gridDim.x - 1 - (int)blockIdx.x;
    const int bh   = blockIdx.y;
    const int b    = bh >> 4, head = bh & 15;
    const size_t base = (size_t)bh * SEQ * DK;
    const int q0 = qt * 128;
    const int NT = 2 * qt + 2;

    #pragma unroll
    for (int j = 0; j < 4; j++){
        int i = j * 256 + tid;
        int r = i >> 3, c16 = i & 7;
        cpa16(sb + SW128((uint32_t)(r << 7) + (c16 << 4)),
              Qg + base + (size_t)(q0 + r) * DK + c16 * 8);
    }
    cp_commit();

    auto load_kv = [&](int kt, int stage){
        uint32_t tb = sb + 16384 + stage * 16384;
        size_t kb = base + (size_t)kt * 64 * DK;
        #pragma unroll
        for (int j = 0; j < 2; j++){
            int i = j * 256 + tid;
            int r = i >> 3, c16 = i & 7;
            uint32_t o = SW128((uint32_t)(r << 7) + (c16 << 4));
            cpa16(tb + o,        Kg + kb + (size_t)r * DK + c16 * 8);
            cpa16(tb + 8192 + o, Vg + kb + (size_t)r * DK + c16 * 8);
        }
        cp_commit();
    };
    load_kv(0, 0);
    load_kv(1, 1);

    cp_wait2();
    __syncthreads();

    uint32_t qf[4][4];
    #pragma unroll
    for (int s = 0; s < 4; s++){
        uint32_t o = (uint32_t)((w*16 + (lane & 15)) << 7) + s*32 + ((lane >> 4) << 4);
        ldsm4(qf[s], sb + SW128(o));
    }

    float oacc[8][4];
    #pragma unroll
    for (int i = 0; i < 8; i++)
        #pragma unroll
        for (int j = 0; j < 4; j++) oacc[i][j] = 0.0f;
    float m0 = -1e30f, m1 = -1e30f, l0 = 0.0f, l1 = 0.0f;
    const int qrow0 = q0 + w * 16;

    for (int kt = 0; kt < NT; kt++){
        if (kt + 1 < NT) cp_wait1(); else cp_wait0();
        __syncthreads();
        uint32_t tb = sb + 16384 + (kt % 3) * 16384;

        float sc[8][4];
        #pragma unroll
        for (int i = 0; i < 8; i++)
            #pragma unroll
            for (int j = 0; j < 4; j++) sc[i][j] = 0.0f;

        #pragma unroll
        for (int s = 0; s < 4; s++){
            uint32_t kf[4][4];
            #pragma unroll
            for (int g = 0; g < 4; g++){
                uint32_t o = (uint32_t)((g*16 + (lane & 15)) << 7) + s*32 + ((lane >> 4) << 4);
                ldsm4(kf[g], tb + SW128(o));
            }
            #pragma unroll
            for (int g = 0; g < 4; g++)
                #pragma unroll
                for (int j = 0; j < 2; j++)
                    mma16816(sc[g*2+j], qf[s], kf[g][j], kf[g][j+2]);
        }

        if (kt*64 + 63 > qrow0){
            int r0 = qrow0 + gid, r1 = r0 + 8;
            #pragma unroll
            for (int tn = 0; tn < 8; tn++){
                int key = kt*64 + tn*8 + tig*2;
                if (key     > r0) sc[tn][0] = -1e9f;
                if (key + 1 > r0) sc[tn][1] = -1e9f;
                if (key     > r1) sc[tn][2] = -1e9f;
                if (key + 1 > r1) sc[tn][3] = -1e9f;
            }
        }

        float t0 = -1e30f, t1 = -1e30f;
        #pragma unroll
        for (int tn = 0; tn < 8; tn++){
            t0 = fmaxf(t0, fmaxf(sc[tn][0], sc[tn][1]));
            t1 = fmaxf(t1, fmaxf(sc[tn][2], sc[tn][3]));
        }
        t0 = fmaxf(t0, __shfl_xor_sync(0xffffffffu, t0, 1));
        t0 = fmaxf(t0, __shfl_xor_sync(0xffffffffu, t0, 2));
        t1 = fmaxf(t1, __shfl_xor_sync(0xffffffffu, t1, 1));
        t1 = fmaxf(t1, __shfl_xor_sync(0xffffffffu, t1, 2));
        float nm0 = fmaxf(m0, t0), nm1 = fmaxf(m1, t1);
        float c0 = __expf(m0 - nm0), c1 = __expf(m1 - nm1);
        l0 *= c0; l1 *= c1;
        #pragma unroll
        for (int tn = 0; tn < 8; tn++){
            sc[tn][0] = __expf(sc[tn][0] - nm0);
            sc[tn][1] = __expf(sc[tn][1] - nm0);
            sc[tn][2] = __expf(sc[tn][2] - nm1);
            sc[tn][3] = __expf(sc[tn][3] - nm1);
            l0 += sc[tn][0] + sc[tn][1];
            l1 += sc[tn][2] + sc[tn][3];
        }
        #pragma unroll
        for (int od = 0; od < 8; od++){
            oacc[od][0] *= c0; oacc[od][1] *= c0;
            oacc[od][2] *= c1; oacc[od][3] *= c1;
        }
        m0 = nm0; m1 = nm1;

        uint32_t pf[4][4];
        #pragma unroll
        for (int s = 0; s < 4; s++){
            pf[s][0] = f22h(sc[2*s][0],   sc[2*s][1]);
            pf[s][1] = f22h(sc[2*s][2],   sc[2*s][3]);
            pf[s][2] = f22h(sc[2*s+1][0], sc[2*s+1][1]);
            pf[s][3] = f22h(sc[2*s+1][2], sc[2*s+1][3]);
        }

        #pragma unroll
        for (int s = 0; s < 4; s++){
            uint32_t vf[4][4];
            #pragma unroll
            for (int gd = 0; gd < 4; gd++){
                uint32_t row = s*16 + (lane & 7) + ((lane & 16) >> 1);
                uint32_t col = gd*16 + (lane & 8);
                ldsm4t(vf[gd], tb + 8192 + SW128((row << 7) + (col << 1)));
            }
            #pragma unroll
            for (int gd = 0; gd < 4; gd++)
                #pragma unroll
                for (int j = 0; j < 2; j++)
                    mma16816(oacc[gd*2+j], pf[s], vf[gd][j], vf[gd][j+2]);
        }

        if (kt + 2 < NT) load_kv(kt + 2, (kt + 2) % 3);
    }

    l0 += __shfl_xor_sync(0xffffffffu, l0, 1);
    l0 += __shfl_xor_sync(0xffffffffu, l0, 2);
    l1 += __shfl_xor_sync(0xffffffffu, l1, 1);
    l1 += __shfl_xor_sync(0xffffffffu, l1, 2);
    float inv0 = 1.0f / l0, inv1 = 1.0f / l1;

    int q = qrow0 + gid;
    size_t tk0 = (size_t)(b * SEQ + q) * DM + head * 64;
    size_t tk1 = tk0 + (size_t)8 * DM;
    #pragma unroll
    for (int od = 0; od < 8; od++){
        int d = od*8 + tig*2;
        *(uint32_t*)(Og + tk0 + d) = f22h(oacc[od][0] * inv0, oacc[od][1] * inv0);
        *(uint32_t*)(Og + tk1 + d) = f22h(oacc[od][2] * inv1, oacc[od][3] * inv1);
    }
}

// ---------------- launch ----------------
extern "C" void kernel_launch(void* const* d_in, const int* in_sizes, int n_in,
                              void* d_out, int out_size)
{
    const float* x  = (const float*)d_in[0];
    const float* Wq = (const float*)d_in[1];
    const float* Wk = (const float*)d_in[2];
    const float* Wv = (const float*)d_in[3];
    const float* Wo = (const float*)d_in[4];
    const float* g1 = (const float*)d_in[5];
    const float* g2 = (const float*)d_in[6];
    const float* W1 = (const float*)d_in[7];
    const float* W3 = (const float*)d_in[8];
    const float* W2 = (const float*)d_in[9];
    float* out = (float*)d_out;

    float *x1;
    __half *h1,*at,*h2,*gb,*w,*q,*k,*v;
    cudaGetSymbolAddress((void**)&x1, g_x1);
    cudaGetSymbolAddress((void**)&h1, g_h1);
    cudaGetSymbolAddress((void**)&at, g_at);
    cudaGetSymbolAddress((void**)&h2, g_h2);
    cudaGetSymbolAddress((void**)&gb, g_gb);
    cudaGetSymbolAddress((void**)&w,  g_w);
    cudaGetSymbolAddress((void**)&q,  g_q);
    cudaGetSymbolAddress((void**)&k,  g_k);
    cudaGetSymbolAddress((void**)&v,  g_v);

    cudaFuncSetAttribute(gemm_qkv, cudaFuncAttributeMaxDynamicSharedMemorySize, G64_SMEM);
    cudaFuncSetAttribute(gemm_add, cudaFuncAttributeMaxDynamicSharedMemorySize, G64_SMEM);
    cudaFuncSetAttribute(gemm_w13, cudaFuncAttributeMaxDynamicSharedMemorySize, W13_SMEM);
    cudaFuncSetAttribute(flash_tc, cudaFuncAttributeMaxDynamicSharedMemorySize, FA_SMEM);

    rope_table_k<<<SEQ * 32 / 256, 256>>>();
    cvt_all_k<<<4096, 256>>>(Wq, Wk, Wv, Wo, W1, W3, W2, w);

    rms_h_k<<<TOKENS, 256>>>(x, g1, h1);

    gemm_qkv<<<dim3(3*DM/128, TOKENS/128), 256, G64_SMEM>>>(h1, w, q, k, v);

    flash_tc<<<dim3(SEQ / 128, 2 * NH), 256, FA_SMEM>>>(q, k, v, at);

    gemm_add<<<dim3(DM/128, TOKENS/128), 256, G64_SMEM>>>(at, w + WOFF_O, x1, x, DM, DM);
    rms_h_k<<<TOKENS, 256>>>(x1, g2, h2);

    gemm_w13<<<dim3(DFF/64, TOKENS/128), 256, W13_SMEM>>>(h2, w + WOFF_1, w + WOFF_3, gb);
    gemm_add<<<dim3(DM/128, TOKENS/128), 256, G64_SMEM>>>(gb, w + WOFF_2, out, x1, DM, DFF);
}

// round 13
// speedup vs baseline: 1.0004x; 1.0004x over previous
#include <cuda_runtime.h>
#include <cuda_fp16.h>
#include <math.h>
#include <stdint.h>

#define TOKENS 4096
#define DM     1024
#define DFF    4096
#define SEQ    2048
#define NH     16
#define DK     64

// ---------------- scratch ----------------
__device__ float g_x1[TOKENS*DM];
__device__ float g_cs[SEQ*32];
__device__ float g_sn[SEQ*32];

__device__ __half g_h1[TOKENS*DM];
__device__ __half g_at[TOKENS*DM];
__device__ __half g_h2[TOKENS*DM];
__device__ __half g_gb[TOKENS*DFF];
__device__ __half g_q[TOKENS*DM];
__device__ __half g_k[TOKENS*DM];
__device__ __half g_v[TOKENS*DM];

#define WOFF_Q  0
#define WOFF_K  (1u<<20)
#define WOFF_V  (2u<<20)
#define WOFF_O  (3u<<20)
#define WOFF_1  (4u<<20)
#define WOFF_3  (8u<<20)
#define WOFF_2  (12u<<20)
__device__ __half g_w[16u<<20];

// ---------------- helpers ----------------
__device__ __forceinline__ uint32_t smem_u32(const void* p){
    uint32_t r;
    asm("{ .reg .u64 t; cvta.to.shared.u64 t, %1; cvt.u32.u64 %0, t; }" : "=r"(r) : "l"(p));
    return r;
}
__device__ __forceinline__ void cpa16(uint32_t dst, const void* src){
    asm volatile("cp.async.cg.shared.global [%0], [%1], 16;" :: "r"(dst), "l"(src) : "memory");
}
__device__ __forceinline__ void cp_commit(){ asm volatile("cp.async.commit_group;" ::: "memory"); }
__device__ __forceinline__ void cp_wait2(){ asm volatile("cp.async.wait_group 2;" ::: "memory"); }
__device__ __forceinline__ void cp_wait1(){ asm volatile("cp.async.wait_group 1;" ::: "memory"); }
__device__ __forceinline__ void cp_wait0(){ asm volatile("cp.async.wait_group 0;" ::: "memory"); }

__device__ __forceinline__ void ldsm4(uint32_t* r, uint32_t addr){
    asm volatile("ldmatrix.sync.aligned.m8n8.x4.shared.b16 {%0,%1,%2,%3}, [%4];"
        : "=r"(r[0]),"=r"(r[1]),"=r"(r[2]),"=r"(r[3]) : "r"(addr));
}
__device__ __forceinline__ void ldsm4t(uint32_t* r, uint32_t addr){
    asm volatile("ldmatrix.sync.aligned.m8n8.x4.trans.shared.b16 {%0,%1,%2,%3}, [%4];"
        : "=r"(r[0]),"=r"(r[1]),"=r"(r[2]),"=r"(r[3]) : "r"(addr));
}
__device__ __forceinline__ void mma16816(float* c, const uint32_t* a, uint32_t b0, uint32_t b1){
    asm volatile("mma.sync.aligned.m16n8k16.row.col.f32.f16.f16.f32 "
        "{%0,%1,%2,%3}, {%4,%5,%6,%7}, {%8,%9}, {%0,%1,%2,%3};"
        : "+f"(c[0]),"+f"(c[1]),"+f"(c[2]),"+f"(c[3])
        : "r"(a[0]),"r"(a[1]),"r"(a[2]),"r"(a[3]), "r"(b0),"r"(b1));
}
#define SW128(o) ((o) ^ (((o)>>3)&0x70))

__device__ __forceinline__ uint32_t f22h(float x, float y){
    __half2 h = __floats2half2_rn(x, y);
    return *reinterpret_cast<uint32_t*>(&h);
}

// ---------------- RoPE table ----------------
__global__ void rope_table_k() {
    __shared__ float invf[32];
    int t = threadIdx.x;
    if (t < 32) invf[t] = (float)pow(10000.0, -(double)(2 * t) / 64.0);
    __syncthreads();
    int i = blockIdx.x * 256 + t;
    int pos = i >> 5;
    int j   = i & 31;
    float ang = (float)pos * invf[j];
    g_cs[i] = cosf(ang);
    g_sn[i] = sinf(ang);
}

// ---------------- all weight conversions fp32 -> fp16 ----------------
__global__ void cvt_all_k(const float* __restrict__ Wq, const float* __restrict__ Wk,
                          const float* __restrict__ Wv, const float* __restrict__ Wo,
                          const float* __restrict__ W1, const float* __restrict__ W3,
                          const float* __restrict__ W2, __half* __restrict__ w){
    int gb = blockIdx.x;
    const float* src; uint32_t woff; int lb;
    if (gb < 1024){
        int m = gb >> 8; lb = gb & 255;
        src = (m==0)?Wq:(m==1)?Wk:(m==2)?Wv:Wo;
        woff = (uint32_t)m << 20;
    } else if (gb < 2048){ src = W1; woff = WOFF_1; lb = gb - 1024; }
    else if (gb < 3072){ src = W3; woff = WOFF_3; lb = gb - 2048; }
    else               { src = W2; woff = WOFF_2; lb = gb - 3072; }
    uint2* hp = (uint2*)(w + woff);
    #pragma unroll
    for (int j = 0; j < 4; j++){
        int i4 = lb * 1024 + j * 256 + threadIdx.x;
        float4 v = ((const float4*)src)[i4];
        hp[i4] = make_uint2(f22h(v.x, v.y), f22h(v.z, v.w));
    }
}

// ---------------- RMSNorm -> fp16 ----------------
__global__ __launch_bounds__(256) void rms_h_k(const float* __restrict__ x,
                                               const float* __restrict__ g,
                                               __half* __restrict__ o) {
    int row = blockIdx.x;
    int t   = threadIdx.x;
    const float4* xr = (const float4*)(x + (size_t)row * DM);
    float4 xv = xr[t];
    float ss = xv.x*xv.x + xv.y*xv.y + xv.z*xv.z + xv.w*xv.w;
    #pragma unroll
    for (int off = 16; off > 0; off >>= 1)
        ss += __shfl_xor_sync(0xffffffffu, ss, off);
    __shared__ float warpsum[8];
    if ((t & 31) == 0) warpsum[t >> 5] = ss;
    __syncthreads();
    float tot = warpsum[0]+warpsum[1]+warpsum[2]+warpsum[3]
              + warpsum[4]+warpsum[5]+warpsum[6]+warpsum[7];
    float r = rsqrtf(tot * (1.0f / (float)DM) + 1e-5f);
    float4 gv = ((const float4*)g)[t];
    size_t base4 = (size_t)row * (DM/4) + t;
    ((uint2*)o)[base4] = make_uint2(f22h(xv.x*r*gv.x, xv.y*r*gv.y),
                                    f22h(xv.z*r*gv.z, xv.w*r*gv.w));
}

// =====================================================================
// fp16 GEMM engine (R10 config): CTA 128x64, 256 thr (2 CTAs/SM),
// warp 4x2 of 32x32, BK=64, SW128 128B rows, 3-stage.
// Stage (24 KB): A@0(16K) B@16K(8K).
// LDSM addresses hoisted: addr(s) = (tb + base) ^ (s*32).
// =====================================================================
#define STGH     24576
#define GH_SMEM  (3*STGH)

__device__ __forceinline__ void gh_load(
    uint32_t tb, int tid, int m0, int n0, int kc, int K,
    const __half* A, const __half* B)
{
    int k0 = kc * 64;
    #pragma unroll
    for (int j = 0; j < 4; j++){
        int i = j * 256 + tid;
        int r = i >> 3, c16 = i & 7;
        cpa16(tb + SW128((uint32_t)(r << 7) + (c16 << 4)),
              A + (size_t)(m0 + r) * K + k0 + c16 * 8);
    }
    #pragma unroll
    for (int j = 0; j < 2; j++){
        int i = j * 256 + tid;
        int r = i >> 3, c16 = i & 7;
        cpa16(tb + 16384 + SW128((uint32_t)(r << 7) + (c16 << 4)),
              B + (size_t)(n0 + r) * K + k0 + c16 * 8);
    }
    cp_commit();
}

// precomputed swizzled base offsets for the warp's fragments (s=0)
struct GhBase { uint32_t a[2], b[2]; };
__device__ __forceinline__ GhBase gh_bases(int lane, int wm, int wn){
    GhBase gb;
    uint32_t colb = (uint32_t)((lane >> 4) << 4);
    #pragma unroll
    for (int t = 0; t < 2; t++)
        gb.a[t] = SW128((uint32_t)((wm*32 + t*16 + (lane & 15)) << 7) + colb);
    #pragma unroll
    for (int g = 0; g < 2; g++)
        gb.b[g] = 16384 + SW128((uint32_t)((wn*32 + g*16 + (lane & 15)) << 7) + colb);
    return gb;
}

struct FragsH { uint32_t a[2][4], b[2][4]; };

__device__ __forceinline__ void gh_ldfrag(FragsH& f, uint32_t tb, const GhBase& gb, int s){
    uint32_t sx = (uint32_t)(s * 32);
    #pragma unroll
    for (int t = 0; t < 2; t++)
        ldsm4(f.a[t], (tb + gb.a[t]) ^ sx);
    #pragma unroll
    for (int g = 0; g < 2; g++)
        ldsm4(f.b[g], (tb + gb.b[g]) ^ sx);
}

__device__ __forceinline__ void gh_mma(float acc[2][4][4], const FragsH& f){
    #pragma unroll
    for (int t = 0; t < 2; t++)
        #pragma unroll
        for (int g = 0; g < 2; g++)
            #pragma unroll
            for (int j = 0; j < 2; j++)
                mma16816(acc[t][g*2+j], f.a[t], f.b[g][j], f.b[g][j+2]);
}

__device__ __forceinline__ void gh_chunk(uint32_t tb, const GhBase& gb, float acc[2][4][4]){
    FragsH f0, f1;
    gh_ldfrag(f0, tb, gb, 0);
    gh_ldfrag(f1, tb, gb, 1);
    gh_mma(acc, f0);
    gh_ldfrag(f0, tb, gb, 2);
    gh_mma(acc, f1);
    gh_ldfrag(f1, tb, gb, 3);
    gh_mma(acc, f0);
    gh_mma(acc, f1);
}

#define GH_MAIN(A_, B_, KDIM)                                                 \
    GhBase gbse = gh_bases(lane, wm, wn);                                     \
    gh_load(sb, tid, m0, n0, 0, KDIM, A_, B_);                                \
    gh_load(sb + STGH, tid, m0, n0, 1, KDIM, A_, B_);                         \
    for (int kc = 0; kc < NC; kc++){                                          \
        if (kc + 1 < NC) cp_wait1(); else cp_wait0();                         \
        __syncthreads();                                                      \
        if (kc + 2 < NC)                                                      \
            gh_load(sb + ((kc+2)%3)*STGH, tid, m0, n0, kc+2, KDIM, A_, B_);   \
        gh_chunk(sb + (kc%3)*STGH, gbse, acc);                                \
    }

// ---------------- fused QKV GEMM (N=3072) ----------------
__global__ __launch_bounds__(256, 2) void gemm_qkv(
    const __half* __restrict__ A, const __half* __restrict__ B,
    __half* __restrict__ Q, __half* __restrict__ K_, __half* __restrict__ V)
{
    extern __shared__ char smem[];
    uint32_t sb = smem_u32(smem);
    const int tid  = threadIdx.x;
    const int lane = tid & 31;
    const int wid  = tid >> 5;
    const int wm   = wid & 3;
    const int wn   = wid >> 2;
    const int m0 = blockIdx.y * 128, n0 = blockIdx.x * 64;
    const int NC = DM / 64;

    float acc[2][4][4];
    #pragma unroll
    for (int i = 0; i < 2; i++)
        #pragma unroll
        for (int j = 0; j < 4; j++)
            #pragma unroll
            for (int kk = 0; kk < 4; kk++) acc[i][j][kk] = 0.0f;

    GH_MAIN(A, B, DM)

    const int mtx = n0 >> 10;
    const float scl = (mtx == 0) ? 0.125f : 1.0f;
    __half* D = (mtx==0)?Q:(mtx==1)?K_:V;
    const int gid = lane >> 2, tig = lane & 3;
    #pragma unroll
    for (int tm = 0; tm < 2; tm++){
        #pragma unroll
        for (int half = 0; half < 2; half++){
            int m = m0 + wm*32 + tm*16 + gid + half*8;
            int pos = m & (SEQ - 1), b = m >> 11;
            #pragma unroll
            for (int tn = 0; tn < 4; tn++){
                int cc = (n0 & 1023) + wn*32 + tn*8 + tig*2;
                int head = cc >> 6, hi = cc & 63;
                size_t ob = ((size_t)(b * NH + head) * SEQ + pos) * DK + hi;
                float v0 = acc[tm][tn][half*2];
                float v1 = acc[tm][tn][half*2 + 1];
                float w0, w1;
                if (mtx < 2){
                    float cs = g_cs[pos * 32 + (hi >> 1)];
                    float sn = g_sn[pos * 32 + (hi >> 1)];
                    w0 = (v0 * cs - v1 * sn) * scl;
                    w1 = (v0 * sn + v1 * cs) * scl;
                } else { w0 = v0; w1 = v1; }
                *(uint32_t*)(D + ob) = f22h(w0, w1);
            }
        }
    }
}

// ---------------- GEMM + residual add (Wo, W2) ----------------
__global__ __launch_bounds__(256, 2) void gemm_add(
    const __half* __restrict__ A, const __half* __restrict__ B,
    float* __restrict__ C, const float* __restrict__ other, int N, int K)
{
    extern __shared__ char smem[];
    uint32_t sb = smem_u32(smem);
    const int tid  = threadIdx.x;
    const int lane = tid & 31;
    const int wid  = tid >> 5;
    const int wm   = wid & 3;
    const int wn   = wid >> 2;
    const int m0 = blockIdx.y * 128, n0 = blockIdx.x * 64;
    const int NC = K / 64;

    float acc[2][4][4];
    #pragma unroll
    for (int i = 0; i < 2; i++)
        #pragma unroll
        for (int j = 0; j < 4; j++)
            #pragma unroll
            for (int kk = 0; kk < 4; kk++) acc[i][j][kk] = 0.0f;

    GH_MAIN(A, B, K)

    const int gid = lane >> 2, tig = lane & 3;
    #pragma unroll
    for (int tm = 0; tm < 2; tm++){
        #pragma unroll
        for (int half = 0; half < 2; half++){
            int m = m0 + wm*32 + tm*16 + gid + half*8;
            #pragma unroll
            for (int tn = 0; tn < 4; tn++){
                int c = n0 + wn*32 + tn*8 + tig*2;
                size_t base = (size_t)m * N + c;
                C[base]     = other[base] + acc[tm][tn][half*2];
                C[base + 1] = other[base + 1] + acc[tm][tn][half*2 + 1];
            }
        }
    }
}

// ---------------- fused W1/W3 GEMM + silu(u)*v -> fp16 (R10 config) ----------------
#define W13_STG   32768
#define W13_SMEM  (3*W13_STG)

__global__ __launch_bounds__(256, 2) void gemm_w13(
    const __half* __restrict__ A,
    const __half* __restrict__ B1, const __half* __restrict__ B3,
    __half* __restrict__ Cg)
{
    extern __shared__ char smem[];
    uint32_t sb = smem_u32(smem);
    const int tid  = threadIdx.x;
    const int lane = tid & 31;
    const int wid  = tid >> 5;
    const int wm   = wid & 3;
    const int wn   = wid >> 2;
    const int m0 = blockIdx.y * 128, n0 = blockIdx.x * 64;
    const int NC = DM / 64;
    const int K  = DM;

    float accU[2][4][4], accV[2][4][4];
    #pragma unroll
    for (int i = 0; i < 2; i++)
        #pragma unroll
        for (int j = 0; j < 4; j++)
            #pragma unroll
            for (int kk = 0; kk < 4; kk++){ accU[i][j][kk] = 0.0f; accV[i][j][kk] = 0.0f; }

    auto load_chunk = [&](int kc, int stage){
        uint32_t tb = sb + stage * W13_STG;
        int k0 = kc * 64;
        #pragma unroll
        for (int j = 0; j < 4; j++){
            int i = j * 256 + tid;
            int r = i >> 3, c16 = i & 7;
            cpa16(tb + SW128((uint32_t)(r << 7) + (c16 << 4)),
                  A + (size_t)(m0 + r) * K + k0 + c16 * 8);
        }
        #pragma unroll
        for (int j = 0; j < 2; j++){
            int i = j * 256 + tid;
            int r = i >> 3, c16 = i & 7;
            uint32_t o = SW128((uint32_t)(r << 7) + (c16 << 4));
            cpa16(tb + 16384 + o, B1 + (size_t)(n0 + r) * K + k0 + c16 * 8);
            cpa16(tb + 24576 + o, B3 + (size_t)(n0 + r) * K + k0 + c16 * 8);
        }
        cp_commit();
    };

    // precomputed fragment bases (s=0)
    uint32_t abase[2], b1base[2], b3base[2];
    {
        uint32_t colb = (uint32_t)((lane >> 4) << 4);
        #pragma unroll
        for (int t = 0; t < 2; t++)
            abase[t] = SW128((uint32_t)((wm*32 + t*16 + (lane & 15)) << 7) + colb);
        #pragma unroll
        for (int g = 0; g < 2; g++){
            uint32_t so = SW128((uint32_t)((wn*32 + g*16 + (lane & 15)) << 7) + colb);
            b1base[g] = 16384 + so;
            b3base[g] = 24576 + so;
        }
    }

    load_chunk(0, 0);
    load_chunk(1, 1);

    for (int kc = 0; kc < NC; kc++){
        if (kc + 1 < NC) cp_wait1(); else cp_wait0();
        __syncthreads();
        if (kc + 2 < NC) load_chunk(kc + 2, (kc + 2) % 3);
        uint32_t tb = sb + (kc % 3) * W13_STG;

        #pragma unroll
        for (int s = 0; s < 4; s++){
            uint32_t sx = (uint32_t)(s * 32);
            uint32_t a[2][4], b1[2][4], b3[2][4];
            #pragma unroll
            for (int t = 0; t < 2; t++)
                ldsm4(a[t], (tb + abase[t]) ^ sx);
            #pragma unroll
            for (int g = 0; g < 2; g++){
                ldsm4(b1[g], (tb + b1base[g]) ^ sx);
                ldsm4(b3[g], (tb + b3base[g]) ^ sx);
            }
            #pragma unroll
            for (int t = 0; t < 2; t++)
                #pragma unroll
                for (int g = 0; g < 2; g++)
                    #pragma unroll
                    for (int j = 0; j < 2; j++){
                        mma16816(accU[t][g*2+j], a[t], b1[g][j], b1[g][j+2]);
                        mma16816(accV[t][g*2+j], a[t], b3[g][j], b3[g][j+2]);
                    }
        }
    }

    const int gid = lane >> 2, tig = lane & 3;
    #pragma unroll
    for (int tm = 0; tm < 2; tm++){
        #pragma unroll
        for (int half = 0; half < 2; half++){
            int m = m0 + wm*32 + tm*16 + gid + half*8;
            #pragma unroll
            for (int tn = 0; tn < 4; tn++){
                int c = n0 + wn*32 + tn*8 + tig*2;
                size_t base = (size_t)m * DFF + c;
                float u0 = accU[tm][tn][half*2], u1 = accU[tm][tn][half*2+1];
                float v0 = accV[tm][tn][half*2], v1 = accV[tm][tn][half*2+1];
                float w0 = v0 * u0 / (1.0f + __expf(-u0));
                float w1 = v1 * u1 / (1.0f + __expf(-u1));
                *(uint32_t*)(Cg + base) = f22h(w0, w1);
            }
        }
    }
}

// ---------------- fp16 flash attention (causal) ----------------
#define FA_SMEM (16384 + 3*16384)

__global__ __launch_bounds__(256, 2) void flash_tc(
    const __half* __restrict__ Qg, const __half* __restrict__ Kg,
    const __half* __restrict__ Vg, __half* __restrict__ Og)
{
    extern __shared__ char smem[];
    uint32_t sb = smem_u32(smem);
    const int tid  = threadIdx.x;
    const int lane = tid & 31;
    const int w    = tid >> 5;
    const int gid  = lane >> 2, tig = lane & 3;
    const int qt   = (int)gridDim.x - 1 - (int)blockIdx.x;
    const int bh   = blockIdx.y;
    const int b    = bh >> 4, head = bh & 15;
    const size_t base = (size_t)bh * SEQ * DK;
    const int q0 = qt * 128;
    const int NT = 2 * qt + 2;

    #pragma unroll
    for (int j = 0; j < 4; j++){
        int i = j * 256 + tid;
        int r = i >> 3, c16 = i & 7;
        cpa16(sb + SW128((uint32_t)(r << 7) + (c16 << 4)),
              Qg + base + (size_t)(q0 + r) * DK + c16 * 8);
    }
    cp_commit();

    auto load_kv = [&](int kt, int stage){
        uint32_t tb = sb + 16384 + stage * 16384;
        size_t kb = base + (size_t)kt * 64 * DK;
        #pragma unroll
        for (int j = 0; j < 2; j++){
            int i = j * 256 + tid;
            int r = i >> 3, c16 = i & 7;
            uint32_t o = SW128((uint32_t)(r << 7) + (c16 << 4));
            cpa16(tb + o,        Kg + kb + (size_t)r * DK + c16 * 8);
            cpa16(tb + 8192 + o, Vg + kb + (size_t)r * DK + c16 * 8);
        }
        cp_commit();
    };
    load_kv(0, 0);
    load_kv(1, 1);

    // precomputed K fragment bases (s=0): rows g*16+(lane&15), col (lane>>4)<<4
    uint32_t kbase[4];
    #pragma unroll
    for (int g = 0; g < 4; g++)
        kbase[g] = SW128((uint32_t)((g*16 + (lane & 15)) << 7) + ((lane >> 4) << 4));

    cp_wait2();
    __syncthreads();

    uint32_t qf[4][4];
    #pragma unroll
    for (int s = 0; s < 4; s++){
        uint32_t o = (uint32_t)((w*16 + (lane & 15)) << 7) + s*32 + ((lane >> 4) << 4);
        ldsm4(qf[s], sb + SW128(o));
    }

    float oacc[8][4];
    #pragma unroll
    for (int i = 0; i < 8; i++)
        #pragma unroll
        for (int j = 0; j < 4; j++) oacc[i][j] = 0.0f;
    float m0 = -1e30f, m1 = -1e30f, l0 = 0.0f, l1 = 0.0f;
    const int qrow0 = q0 + w * 16;

    for (int kt = 0; kt < NT; kt++){
        if (kt + 1 < NT) cp_wait1(); else cp_wait0();
        __syncthreads();
        uint32_t tb = sb + 16384 + (kt % 3) * 16384;

        float sc[8][4];
        #pragma unroll
        for (int i = 0; i < 8; i++)
            #pragma unroll
            for (int j = 0; j < 4; j++) sc[i][j] = 0.0f;

        #pragma unroll
        for (int s = 0; s < 4; s++){
            uint32_t sx = (uint32_t)(s * 32);
            uint32_t kf[4][4];
            #pragma unroll
            for (int g = 0; g < 4; g++)
                ldsm4(kf[g], (tb + kbase[g]) ^ sx);
            #pragma unroll
            for (int g = 0; g < 4; g++)
                #pragma unroll
                for (int j = 0; j < 2; j++)
                    mma16816(sc[g*2+j], qf[s], kf[g][j], kf[g][j+2]);
        }

        if (kt*64 + 63 > qrow0){
            int r0 = qrow0 + gid, r1 = r0 + 8;
            #pragma unroll
            for (int tn = 0; tn < 8; tn++){
                int key = kt*64 + tn*8 + tig*2;
                if (key     > r0) sc[tn][0] = -1e9f;
                if (key + 1 > r0) sc[tn][1] = -1e9f;
                if (key     > r1) sc[tn][2] = -1e9f;
                if (key + 1 > r1) sc[tn][3] = -1e9f;
            }
        }

        float t0 = -1e30f, t1 = -1e30f;
        #pragma unroll
        for (int tn = 0; tn < 8; tn++){
            t0 = fmaxf(t0, fmaxf(sc[tn][0], sc[tn][1]));
            t1 = fmaxf(t1, fmaxf(sc[tn][2], sc[tn][3]));
        }
        t0 = fmaxf(t0, __shfl_xor_sync(0xffffffffu, t0, 1));
        t0 = fmaxf(t0, __shfl_xor_sync(0xffffffffu, t0, 2));
        t1 = fmaxf(t1, __shfl_xor_sync(0xffffffffu, t1, 1));
        t1 = fmaxf(t1, __shfl_xor_sync(0xffffffffu, t1, 2));
        float nm0 = fmaxf(m0, t0), nm1 = fmaxf(m1, t1);
        float c0 = __expf(m0 - nm0), c1 = __expf(m1 - nm1);
        l0 *= c0; l1 *= c1;
        #pragma unroll
        for (int tn = 0; tn < 8; tn++){
            sc[tn][0] = __expf(sc[tn][0] - nm0);
            sc[tn][1] = __expf(sc[tn][1] - nm0);
            sc[tn][2] = __expf(sc[tn][2] - nm1);
            sc[tn][3] = __expf(sc[tn][3] - nm1);
            l0 += sc[tn][0] + sc[tn][1];
            l1 += sc[tn][2] + sc[tn][3];
        }
        #pragma unroll
        for (int od = 0; od < 8; od++){
            oacc[od][0] *= c0; oacc[od][1] *= c0;
            oacc[od][2] *= c1; oacc[od][3] *= c1;
        }
        m0 = nm0; m1 = nm1;

        uint32_t pf[4][4];
        #pragma unroll
        for (int s = 0; s < 4; s++){
            pf[s][0] = f22h(sc[2*s][0],   sc[2*s][1]);
            pf[s][1] = f22h(sc[2*s][2],   sc[2*s][3]);
            pf[s][2] = f22h(sc[2*s+1][0], sc[2*s+1][1]);
            pf[s][3] = f22h(sc[2*s+1][2], sc[2*s+1][3]);
        }

        #pragma unroll
        for (int s = 0; s < 4; s++){
            uint32_t vf[4][4];
            #pragma unroll
            for (int gd = 0; gd < 4; gd++){
                uint32_t row = s*16 + (lane & 7) + ((lane & 16) >> 1);
                uint32_t col = gd*16 + (lane & 8);
                ldsm4t(vf[gd], tb + 8192 + SW128((row << 7) + (col << 1)));
            }
            #pragma unroll
            for (int gd = 0; gd < 4; gd++)
                #pragma unroll
                for (int j = 0; j < 2; j++)
                    mma16816(oacc[gd*2+j], pf[s], vf[gd][j], vf[gd][j+2]);
        }

        if (kt + 2 < NT) load_kv(kt + 2, (kt + 2) % 3);
    }

    l0 += __shfl_xor_sync(0xffffffffu, l0, 1);
    l0 += __shfl_xor_sync(0xffffffffu, l0, 2);
    l1 += __shfl_xor_sync(0xffffffffu, l1, 1);
    l1 += __shfl_xor_sync(0xffffffffu, l1, 2);
    float inv0 = 1.0f / l0, inv1 = 1.0f / l1;

    int q = qrow0 + gid;
    size_t tk0 = (size_t)(b * SEQ + q) * DM + head * 64;
    size_t tk1 = tk0 + (size_t)8 * DM;
    #pragma unroll
    for (int od = 0; od < 8; od++){
        int d = od*8 + tig*2;
        *(uint32_t*)(Og + tk0 + d) = f22h(oacc[od][0] * inv0, oacc[od][1] * inv0);
        *(uint32_t*)(Og + tk1 + d) = f22h(oacc[od][2] * inv1, oacc[od][3] * inv1);
    }
}

// ---------------- launch ----------------
extern "C" void kernel_launch(void* const* d_in, const int* in_sizes, int n_in,
                              void* d_out, int out_size)
{
    const float* x  = (const float*)d_in[0];
    const float* Wq = (const float*)d_in[1];
    const float* Wk = (const float*)d_in[2];
    const float* Wv = (const float*)d_in[3];
    const float* Wo = (const float*)d_in[4];
    const float* g1 = (const float*)d_in[5];
    const float* g2 = (const float*)d_in[6];
    const float* W1 = (const float*)d_in[7];
    const float* W3 = (const float*)d_in[8];
    const float* W2 = (const float*)d_in[9];
    float* out = (float*)d_out;

    float *x1;
    __half *h1,*at,*h2,*gb,*w,*q,*k,*v;
    cudaGetSymbolAddress((void**)&x1, g_x1);
    cudaGetSymbolAddress((void**)&h1, g_h1);
    cudaGetSymbolAddress((void**)&at, g_at);
    cudaGetSymbolAddress((void**)&h2, g_h2);
    cudaGetSymbolAddress((void**)&gb, g_gb);
    cudaGetSymbolAddress((void**)&w,  g_w);
    cudaGetSymbolAddress((void**)&q,  g_q);
    cudaGetSymbolAddress((void**)&k,  g_k);
    cudaGetSymbolAddress((void**)&v,  g_v);

    cudaFuncSetAttribute(gemm_qkv, cudaFuncAttributeMaxDynamicSharedMemorySize, GH_SMEM);
    cudaFuncSetAttribute(gemm_add, cudaFuncAttributeMaxDynamicSharedMemorySize, GH_SMEM);
    cudaFuncSetAttribute(gemm_w13, cudaFuncAttributeMaxDynamicSharedMemorySize, W13_SMEM);
    cudaFuncSetAttribute(flash_tc, cudaFuncAttributeMaxDynamicSharedMemorySize, FA_SMEM);

    rope_table_k<<<SEQ * 32 / 256, 256>>>();
    cvt_all_k<<<4096, 256>>>(Wq, Wk, Wv, Wo, W1, W3, W2, w);

    rms_h_k<<<TOKENS, 256>>>(x, g1, h1);

    gemm_qkv<<<dim3(3*DM/64, TOKENS/128), 256, GH_SMEM>>>(h1, w, q, k, v);

    flash_tc<<<dim3(SEQ / 128, 2 * NH), 256, FA_SMEM>>>(q, k, v, at);

    gemm_add<<<dim3(DM/64, TOKENS/128), 256, GH_SMEM>>>(at, w + WOFF_O, x1, x, DM, DM);
    rms_h_k<<<TOKENS, 256>>>(x1, g2, h2);

    gemm_w13<<<dim3(DFF/64, TOKENS/128), 256, W13_SMEM>>>(h2, w + WOFF_1, w + WOFF_3, gb);
    gemm_add<<<dim3(DM/64, TOKENS/128), 256, GH_SMEM>>>(gb, w + WOFF_2, out, x1, DM, DFF);
}

// round 14
// speedup vs baseline: 1.0183x; 1.0178x over previous
#include <cuda_runtime.h>
#include <cuda_fp16.h>
#include <math.h>
#include <stdint.h>

#define TOKENS 4096
#define DM     1024
#define DFF    4096
#define SEQ    2048
#define NH     16
#define DK     64

// ---------------- scratch ----------------
__device__ float g_x1[TOKENS*DM];
__device__ float g_cs[SEQ*32];
__device__ float g_sn[SEQ*32];

__device__ __half g_h1[TOKENS*DM];
__device__ __half g_at[TOKENS*DM];
__device__ __half g_h2[TOKENS*DM];
__device__ __half g_gb[TOKENS*DFF];
__device__ __half g_q[TOKENS*DM];
__device__ __half g_k[TOKENS*DM];
__device__ __half g_v[TOKENS*DM];

#define WOFF_Q  0
#define WOFF_K  (1u<<20)
#define WOFF_V  (2u<<20)
#define WOFF_O  (3u<<20)
#define WOFF_1  (4u<<20)
#define WOFF_3  (8u<<20)
#define WOFF_2  (12u<<20)
__device__ __half g_w[16u<<20];

// ---------------- helpers ----------------
__device__ __forceinline__ uint32_t smem_u32(const void* p){
    uint32_t r;
    asm("{ .reg .u64 t; cvta.to.shared.u64 t, %1; cvt.u32.u64 %0, t; }" : "=r"(r) : "l"(p));
    return r;
}
__device__ __forceinline__ void cpa16(uint32_t dst, const void* src){
    asm volatile("cp.async.cg.shared.global [%0], [%1], 16;" :: "r"(dst), "l"(src) : "memory");
}
__device__ __forceinline__ void cp_commit(){ asm volatile("cp.async.commit_group;" ::: "memory"); }
__device__ __forceinline__ void cp_wait2(){ asm volatile("cp.async.wait_group 2;" ::: "memory"); }
__device__ __forceinline__ void cp_wait1(){ asm volatile("cp.async.wait_group 1;" ::: "memory"); }
__device__ __forceinline__ void cp_wait0(){ asm volatile("cp.async.wait_group 0;" ::: "memory"); }

__device__ __forceinline__ void ldsm4(uint32_t* r, uint32_t addr){
    asm volatile("ldmatrix.sync.aligned.m8n8.x4.shared.b16 {%0,%1,%2,%3}, [%4];"
        : "=r"(r[0]),"=r"(r[1]),"=r"(r[2]),"=r"(r[3]) : "r"(addr));
}
__device__ __forceinline__ void ldsm4t(uint32_t* r, uint32_t addr){
    asm volatile("ldmatrix.sync.aligned.m8n8.x4.trans.shared.b16 {%0,%1,%2,%3}, [%4];"
        : "=r"(r[0]),"=r"(r[1]),"=r"(r[2]),"=r"(r[3]) : "r"(addr));
}
__device__ __forceinline__ void mma16816(float* c, const uint32_t* a, uint32_t b0, uint32_t b1){
    asm volatile("mma.sync.aligned.m16n8k16.row.col.f32.f16.f16.f32 "
        "{%0,%1,%2,%3}, {%4,%5,%6,%7}, {%8,%9}, {%0,%1,%2,%3};"
        : "+f"(c[0]),"+f"(c[1]),"+f"(c[2]),"+f"(c[3])
        : "r"(a[0]),"r"(a[1]),"r"(a[2]),"r"(a[3]), "r"(b0),"r"(b1));
}
#define SW128(o) ((o) ^ (((o)>>3)&0x70))

__device__ __forceinline__ uint32_t f22h(float x, float y){
    __half2 h = __floats2half2_rn(x, y);
    return *reinterpret_cast<uint32_t*>(&h);
}

// ---------------- RoPE table ----------------
__global__ void rope_table_k() {
    __shared__ float invf[32];
    int t = threadIdx.x;
    if (t < 32) invf[t] = (float)pow(10000.0, -(double)(2 * t) / 64.0);
    __syncthreads();
    int i = blockIdx.x * 256 + t;
    int pos = i >> 5;
    int j   = i & 31;
    float ang = (float)pos * invf[j];
    g_cs[i] = cosf(ang);
    g_sn[i] = sinf(ang);
}

// ---------------- all weight conversions fp32 -> fp16 ----------------
__global__ void cvt_all_k(const float* __restrict__ Wq, const float* __restrict__ Wk,
                          const float* __restrict__ Wv, const float* __restrict__ Wo,
                          const float* __restrict__ W1, const float* __restrict__ W3,
                          const float* __restrict__ W2, __half* __restrict__ w){
    int gb = blockIdx.x;
    const float* src; uint32_t woff; int lb;
    if (gb < 1024){
        int m = gb >> 8; lb = gb & 255;
        src = (m==0)?Wq:(m==1)?Wk:(m==2)?Wv:Wo;
        woff = (uint32_t)m << 20;
    } else if (gb < 2048){ src = W1; woff = WOFF_1; lb = gb - 1024; }
    else if (gb < 3072){ src = W3; woff = WOFF_3; lb = gb - 2048; }
    else               { src = W2; woff = WOFF_2; lb = gb - 3072; }
    uint2* hp = (uint2*)(w + woff);
    #pragma unroll
    for (int j = 0; j < 4; j++){
        int i4 = lb * 1024 + j * 256 + threadIdx.x;
        float4 v = ((const float4*)src)[i4];
        hp[i4] = make_uint2(f22h(v.x, v.y), f22h(v.z, v.w));
    }
}

// ---------------- RMSNorm -> fp16 ----------------
__global__ __launch_bounds__(256) void rms_h_k(const float* __restrict__ x,
                                               const float* __restrict__ g,
                                               __half* __restrict__ o) {
    int row = blockIdx.x;
    int t   = threadIdx.x;
    const float4* xr = (const float4*)(x + (size_t)row * DM);
    float4 xv = xr[t];
    float ss = xv.x*xv.x + xv.y*xv.y + xv.z*xv.z + xv.w*xv.w;
    #pragma unroll
    for (int off = 16; off > 0; off >>= 1)
        ss += __shfl_xor_sync(0xffffffffu, ss, off);
    __shared__ float warpsum[8];
    if ((t & 31) == 0) warpsum[t >> 5] = ss;
    __syncthreads();
    float tot = warpsum[0]+warpsum[1]+warpsum[2]+warpsum[3]
              + warpsum[4]+warpsum[5]+warpsum[6]+warpsum[7];
    float r = rsqrtf(tot * (1.0f / (float)DM) + 1e-5f);
    float4 gv = ((const float4*)g)[t];
    size_t base4 = (size_t)row * (DM/4) + t;
    ((uint2*)o)[base4] = make_uint2(f22h(xv.x*r*gv.x, xv.y*r*gv.y),
                                    f22h(xv.z*r*gv.z, xv.w*r*gv.w));
}

// =====================================================================
// fp16 GEMM engine (R10 config + 4-stage): CTA 128x64, 256 thr
// (2 CTAs/SM), warp 4x2 of 32x32, BK=64, SW128 128B rows.
// Stage (24 KB): A@0(16K) B@16K(8K). 4 stages = 96 KB.
// =====================================================================
#define STGH     24576
#define GH_SMEM  (4*STGH)

__device__ __forceinline__ void gh_load(
    uint32_t tb, int tid, int m0, int n0, int kc, int K,
    const __half* A, const __half* B)
{
    int k0 = kc * 64;
    #pragma unroll
    for (int j = 0; j < 4; j++){
        int i = j * 256 + tid;
        int r = i >> 3, c16 = i & 7;
        cpa16(tb + SW128((uint32_t)(r << 7) + (c16 << 4)),
              A + (size_t)(m0 + r) * K + k0 + c16 * 8);
    }
    #pragma unroll
    for (int j = 0; j < 2; j++){
        int i = j * 256 + tid;
        int r = i >> 3, c16 = i & 7;
        cpa16(tb + 16384 + SW128((uint32_t)(r << 7) + (c16 << 4)),
              B + (size_t)(n0 + r) * K + k0 + c16 * 8);
    }
    cp_commit();
}

struct FragsH { uint32_t a[2][4], b[2][4]; };

__device__ __forceinline__ void gh_ldfrag(FragsH& f, uint32_t tb, int lane, int wm, int wn, int s){
    uint32_t colb = (uint32_t)(s*32) + ((lane >> 4) << 4);
    #pragma unroll
    for (int t = 0; t < 2; t++)
        ldsm4(f.a[t], tb + SW128((uint32_t)((wm*32 + t*16 + (lane & 15)) << 7) + colb));
    #pragma unroll
    for (int g = 0; g < 2; g++)
        ldsm4(f.b[g], tb + 16384 + SW128((uint32_t)((wn*32 + g*16 + (lane & 15)) << 7) + colb));
}

__device__ __forceinline__ void gh_mma(float acc[2][4][4], const FragsH& f){
    #pragma unroll
    for (int t = 0; t < 2; t++)
        #pragma unroll
        for (int g = 0; g < 2; g++)
            #pragma unroll
            for (int j = 0; j < 2; j++)
                mma16816(acc[t][g*2+j], f.a[t], f.b[g][j], f.b[g][j+2]);
}

__device__ __forceinline__ void gh_chunk(uint32_t tb, int lane, int wm, int wn, float acc[2][4][4]){
    FragsH f0, f1;
    gh_ldfrag(f0, tb, lane, wm, wn, 0);
    gh_ldfrag(f1, tb, lane, wm, wn, 1);
    gh_mma(acc, f0);
    gh_ldfrag(f0, tb, lane, wm, wn, 2);
    gh_mma(acc, f1);
    gh_ldfrag(f1, tb, lane, wm, wn, 3);
    gh_mma(acc, f0);
    gh_mma(acc, f1);
}

#define GH_MAIN(A_, B_, KDIM)                                                 \
    gh_load(sb, tid, m0, n0, 0, KDIM, A_, B_);                                \
    gh_load(sb + STGH, tid, m0, n0, 1, KDIM, A_, B_);                         \
    gh_load(sb + 2*STGH, tid, m0, n0, 2, KDIM, A_, B_);                       \
    for (int kc = 0; kc < NC; kc++){                                          \
        if (kc + 2 < NC) cp_wait2();                                          \
        else if (kc + 1 < NC) cp_wait1();                                     \
        else cp_wait0();                                                      \
        __syncthreads();                                                      \
        if (kc + 3 < NC)                                                      \
            gh_load(sb + ((kc+3)&3)*STGH, tid, m0, n0, kc+3, KDIM, A_, B_);   \
        gh_chunk(sb + (kc&3)*STGH, lane, wm, wn, acc);                        \
    }

// ---------------- fused QKV GEMM (N=3072) ----------------
__global__ __launch_bounds__(256, 2) void gemm_qkv(
    const __half* __restrict__ A, const __half* __restrict__ B,
    __half* __restrict__ Q, __half* __restrict__ K_, __half* __restrict__ V)
{
    extern __shared__ char smem[];
    uint32_t sb = smem_u32(smem);
    const int tid  = threadIdx.x;
    const int lane = tid & 31;
    const int wid  = tid >> 5;
    const int wm   = wid & 3;
    const int wn   = wid >> 2;
    const int m0 = blockIdx.y * 128, n0 = blockIdx.x * 64;
    const int NC = DM / 64;

    float acc[2][4][4];
    #pragma unroll
    for (int i = 0; i < 2; i++)
        #pragma unroll
        for (int j = 0; j < 4; j++)
            #pragma unroll
            for (int kk = 0; kk < 4; kk++) acc[i][j][kk] = 0.0f;

    GH_MAIN(A, B, DM)

    const int mtx = n0 >> 10;
    const float scl = (mtx == 0) ? 0.125f : 1.0f;
    __half* D = (mtx==0)?Q:(mtx==1)?K_:V;
    const int gid = lane >> 2, tig = lane & 3;
    #pragma unroll
    for (int tm = 0; tm < 2; tm++){
        #pragma unroll
        for (int half = 0; half < 2; half++){
            int m = m0 + wm*32 + tm*16 + gid + half*8;
            int pos = m & (SEQ - 1), b = m >> 11;
            #pragma unroll
            for (int tn = 0; tn < 4; tn++){
                int cc = (n0 & 1023) + wn*32 + tn*8 + tig*2;
                int head = cc >> 6, hi = cc & 63;
                size_t ob = ((size_t)(b * NH + head) * SEQ + pos) * DK + hi;
                float v0 = acc[tm][tn][half*2];
                float v1 = acc[tm][tn][half*2 + 1];
                float w0, w1;
                if (mtx < 2){
                    float cs = g_cs[pos * 32 + (hi >> 1)];
                    float sn = g_sn[pos * 32 + (hi >> 1)];
                    w0 = (v0 * cs - v1 * sn) * scl;
                    w1 = (v0 * sn + v1 * cs) * scl;
                } else { w0 = v0; w1 = v1; }
                *(uint32_t*)(D + ob) = f22h(w0, w1);
            }
        }
    }
}

// ---------------- GEMM + residual add (Wo, W2) ----------------
__global__ __launch_bounds__(256, 2) void gemm_add(
    const __half* __restrict__ A, const __half* __restrict__ B,
    float* __restrict__ C, const float* __restrict__ other, int N, int K)
{
    extern __shared__ char smem[];
    uint32_t sb = smem_u32(smem);
    const int tid  = threadIdx.x;
    const int lane = tid & 31;
    const int wid  = tid >> 5;
    const int wm   = wid & 3;
    const int wn   = wid >> 2;
    const int m0 = blockIdx.y * 128, n0 = blockIdx.x * 64;
    const int NC = K / 64;

    float acc[2][4][4];
    #pragma unroll
    for (int i = 0; i < 2; i++)
        #pragma unroll
        for (int j = 0; j < 4; j++)
            #pragma unroll
            for (int kk = 0; kk < 4; kk++) acc[i][j][kk] = 0.0f;

    GH_MAIN(A, B, K)

    const int gid = lane >> 2, tig = lane & 3;
    #pragma unroll
    for (int tm = 0; tm < 2; tm++){
        #pragma unroll
        for (int half = 0; half < 2; half++){
            int m = m0 + wm*32 + tm*16 + gid + half*8;
            #pragma unroll
            for (int tn = 0; tn < 4; tn++){
                int c = n0 + wn*32 + tn*8 + tig*2;
                size_t base = (size_t)m * N + c;
                C[base]     = other[base] + acc[tm][tn][half*2];
                C[base + 1] = other[base + 1] + acc[tm][tn][half*2 + 1];
            }
        }
    }
}

// ---------------- fused W1/W3 GEMM + silu(u)*v -> fp16 (3-stage) ----------------
#define W13_STG   32768
#define W13_SMEM  (3*W13_STG)

__global__ __launch_bounds__(256, 2) void gemm_w13(
    const __half* __restrict__ A,
    const __half* __restrict__ B1, const __half* __restrict__ B3,
    __half* __restrict__ Cg)
{
    extern __shared__ char smem[];
    uint32_t sb = smem_u32(smem);
    const int tid  = threadIdx.x;
    const int lane = tid & 31;
    const int wid  = tid >> 5;
    const int wm   = wid & 3;
    const int wn   = wid >> 2;
    const int m0 = blockIdx.y * 128, n0 = blockIdx.x * 64;
    const int NC = DM / 64;
    const int K  = DM;

    float accU[2][4][4], accV[2][4][4];
    #pragma unroll
    for (int i = 0; i < 2; i++)
        #pragma unroll
        for (int j = 0; j < 4; j++)
            #pragma unroll
            for (int kk = 0; kk < 4; kk++){ accU[i][j][kk] = 0.0f; accV[i][j][kk] = 0.0f; }

    auto load_chunk = [&](int kc, int stage){
        uint32_t tb = sb + stage * W13_STG;
        int k0 = kc * 64;
        #pragma unroll
        for (int j = 0; j < 4; j++){
            int i = j * 256 + tid;
            int r = i >> 3, c16 = i & 7;
            cpa16(tb + SW128((uint32_t)(r << 7) + (c16 << 4)),
                  A + (size_t)(m0 + r) * K + k0 + c16 * 8);
        }
        #pragma unroll
        for (int j = 0; j < 2; j++){
            int i = j * 256 + tid;
            int r = i >> 3, c16 = i & 7;
            uint32_t o = SW128((uint32_t)(r << 7) + (c16 << 4));
            cpa16(tb + 16384 + o, B1 + (size_t)(n0 + r) * K + k0 + c16 * 8);
            cpa16(tb + 24576 + o, B3 + (size_t)(n0 + r) * K + k0 + c16 * 8);
        }
        cp_commit();
    };

    load_chunk(0, 0);
    load_chunk(1, 1);

    for (int kc = 0; kc < NC; kc++){
        if (kc + 1 < NC) cp_wait1(); else cp_wait0();
        __syncthreads();
        if (kc + 2 < NC) load_chunk(kc + 2, (kc + 2) % 3);
        uint32_t tb = sb + (kc % 3) * W13_STG;

        #pragma unroll
        for (int s = 0; s < 4; s++){
            uint32_t colb = (uint32_t)(s*32) + ((lane >> 4) << 4);
            uint32_t a[2][4], b1[2][4], b3[2][4];
            #pragma unroll
            for (int t = 0; t < 2; t++)
                ldsm4(a[t], tb + SW128((uint32_t)((wm*32 + t*16 + (lane & 15)) << 7) + colb));
            #pragma unroll
            for (int g = 0; g < 2; g++){
                uint32_t so = SW128((uint32_t)((wn*32 + g*16 + (lane & 15)) << 7) + colb);
                ldsm4(b1[g], tb + 16384 + so);
                ldsm4(b3[g], tb + 24576 + so);
            }
            #pragma unroll
            for (int t = 0; t < 2; t++)
                #pragma unroll
                for (int g = 0; g < 2; g++)
                    #pragma unroll
                    for (int j = 0; j < 2; j++){
                        mma16816(accU[t][g*2+j], a[t], b1[g][j], b1[g][j+2]);
                        mma16816(accV[t][g*2+j], a[t], b3[g][j], b3[g][j+2]);
                    }
        }
    }

    const int gid = lane >> 2, tig = lane & 3;
    #pragma unroll
    for (int tm = 0; tm < 2; tm++){
        #pragma unroll
        for (int half = 0; half < 2; half++){
            int m = m0 + wm*32 + tm*16 + gid + half*8;
            #pragma unroll
            for (int tn = 0; tn < 4; tn++){
                int c = n0 + wn*32 + tn*8 + tig*2;
                size_t base = (size_t)m * DFF + c;
                float u0 = accU[tm][tn][half*2], u1 = accU[tm][tn][half*2+1];
                float v0 = accV[tm][tn][half*2], v1 = accV[tm][tn][half*2+1];
                float w0 = v0 * u0 / (1.0f + __expf(-u0));
                float w1 = v1 * u1 / (1.0f + __expf(-u1));
                *(uint32_t*)(Cg + base) = f22h(w0, w1);
            }
        }
    }
}

// ---------------- fp16 flash attention (causal) ----------------
#define FA_SMEM (16384 + 3*16384)

__global__ __launch_bounds__(256, 2) void flash_tc(
    const __half* __restrict__ Qg, const __half* __restrict__ Kg,
    const __half* __restrict__ Vg, __half* __restrict__ Og)
{
    extern __shared__ char smem[];
    uint32_t sb = smem_u32(smem);
    const int tid  = threadIdx.x;
    const int lane = tid & 31;
    const int w    = tid >> 5;
    const int gid  = lane >> 2, tig = lane & 3;
    const int qt   = (int)gridDim.x - 1 - (int)blockIdx.x;
    const int bh   = blockIdx.y;
    const int b    = bh >> 4, head = bh & 15;
    const size_t base = (size_t)bh * SEQ * DK;
    const int q0 = qt * 128;
    const int NT = 2 * qt + 2;

    #pragma unroll
    for (int j = 0; j < 4; j++){
        int i = j * 256 + tid;
        int r = i >> 3, c16 = i & 7;
        cpa16(sb + SW128((uint32_t)(r << 7) + (c16 << 4)),
              Qg + base + (size_t)(q0 + r) * DK + c16 * 8);
    }
    cp_commit();

    auto load_kv = [&](int kt, int stage){
        uint32_t tb = sb + 16384 + stage * 16384;
        size_t kb = base + (size_t)kt * 64 * DK;
        #pragma unroll
        for (int j = 0; j < 2; j++){
            int i = j * 256 + tid;
            int r = i >> 3, c16 = i & 7;
            uint32_t o = SW128((uint32_t)(r << 7) + (c16 << 4));
            cpa16(tb + o,        Kg + kb + (size_t)r * DK + c16 * 8);
            cpa16(tb + 8192 + o, Vg + kb + (size_t)r * DK + c16 * 8);
        }
        cp_commit();
    };
    load_kv(0, 0);
    load_kv(1, 1);

    cp_wait2();
    __syncthreads();

    uint32_t qf[4][4];
    #pragma unroll
    for (int s = 0; s < 4; s++){
        uint32_t o = (uint32_t)((w*16 + (lane & 15)) << 7) + s*32 + ((lane >> 4) << 4);
        ldsm4(qf[s], sb + SW128(o));
    }

    float oacc[8][4];
    #pragma unroll
    for (int i = 0; i < 8; i++)
        #pragma unroll
        for (int j = 0; j < 4; j++) oacc[i][j] = 0.0f;
    float m0 = -1e30f, m1 = -1e30f, l0 = 0.0f, l1 = 0.0f;
    const int qrow0 = q0 + w * 16;

    for (int kt = 0; kt < NT; kt++){
        if (kt + 1 < NT) cp_wait1(); else cp_wait0();
        __syncthreads();
        uint32_t tb = sb + 16384 + (kt % 3) * 16384;

        float sc[8][4];
        #pragma unroll
        for (int i = 0; i < 8; i++)
            #pragma unroll
            for (int j = 0; j < 4; j++) sc[i][j] = 0.0f;

        #pragma unroll
        for (int s = 0; s < 4; s++){
            uint32_t kf[4][4];
            #pragma unroll
            for (int g = 0; g < 4; g++){
                uint32_t o = (uint32_t)((g*16 + (lane & 15)) << 7) + s*32 + ((lane >> 4) << 4);
                ldsm4(kf[g], tb + SW128(o));
            }
            #pragma unroll
            for (int g = 0; g < 4; g++)
                #pragma unroll
                for (int j = 0; j < 2; j++)
                    mma16816(sc[g*2+j], qf[s], kf[g][j], kf[g][j+2]);
        }

        if (kt*64 + 63 > qrow0){
            int r0 = qrow0 + gid, r1 = r0 + 8;
            #pragma unroll
            for (int tn = 0; tn < 8; tn++){
                int key = kt*64 + tn*8 + tig*2;
                if (key     > r0) sc[tn][0] = -1e9f;
                if (key + 1 > r0) sc[tn][1] = -1e9f;
                if (key     > r1) sc[tn][2] = -1e9f;
                if (key + 1 > r1) sc[tn][3] = -1e9f;
            }
        }

        float t0 = -1e30f, t1 = -1e30f;
        #pragma unroll
        for (int tn = 0; tn < 8; tn++){
            t0 = fmaxf(t0, fmaxf(sc[tn][0], sc[tn][1]));
            t1 = fmaxf(t1, fmaxf(sc[tn][2], sc[tn][3]));
        }
        t0 = fmaxf(t0, __shfl_xor_sync(0xffffffffu, t0, 1));
        t0 = fmaxf(t0, __shfl_xor_sync(0xffffffffu, t0, 2));
        t1 = fmaxf(t1, __shfl_xor_sync(0xffffffffu, t1, 1));
        t1 = fmaxf(t1, __shfl_xor_sync(0xffffffffu, t1, 2));
        float nm0 = fmaxf(m0, t0), nm1 = fmaxf(m1, t1);
        float c0 = __expf(m0 - nm0), c1 = __expf(m1 - nm1);
        l0 *= c0; l1 *= c1;
        #pragma unroll
        for (int tn = 0; tn < 8; tn++){
            sc[tn][0] = __expf(sc[tn][0] - nm0);
            sc[tn][1] = __expf(sc[tn][1] - nm0);
            sc[tn][2] = __expf(sc[tn][2] - nm1);
            sc[tn][3] = __expf(sc[tn][3] - nm1);
            l0 += sc[tn][0] + sc[tn][1];
            l1 += sc[tn][2] + sc[tn][3];
        }
        #pragma unroll
        for (int od = 0; od < 8; od++){
            oacc[od][0] *= c0; oacc[od][1] *= c0;
            oacc[od][2] *= c1; oacc[od][3] *= c1;
        }
        m0 = nm0; m1 = nm1;

        uint32_t pf[4][4];
        #pragma unroll
        for (int s = 0; s < 4; s++){
            pf[s][0] = f22h(sc[2*s][0],   sc[2*s][1]);
            pf[s][1] = f22h(sc[2*s][2],   sc[2*s][3]);
            pf[s][2] = f22h(sc[2*s+1][0], sc[2*s+1][1]);
            pf[s][3] = f22h(sc[2*s+1][2], sc[2*s+1][3]);
        }

        #pragma unroll
        for (int s = 0; s < 4; s++){
            uint32_t vf[4][4];
            #pragma unroll
            for (int gd = 0; gd < 4; gd++){
                uint32_t row = s*16 + (lane & 7) + ((lane & 16) >> 1);
                uint32_t col = gd*16 + (lane & 8);
                ldsm4t(vf[gd], tb + 8192 + SW128((row << 7) + (col << 1)));
            }
            #pragma unroll
            for (int gd = 0; gd < 4; gd++)
                #pragma unroll
                for (int j = 0; j < 2; j++)
                    mma16816(oacc[gd*2+j], pf[s], vf[gd][j], vf[gd][j+2]);
        }

        if (kt + 2 < NT) load_kv(kt + 2, (kt + 2) % 3);
    }

    l0 += __shfl_xor_sync(0xffffffffu, l0, 1);
    l0 += __shfl_xor_sync(0xffffffffu, l0, 2);
    l1 += __shfl_xor_sync(0xffffffffu, l1, 1);
    l1 += __shfl_xor_sync(0xffffffffu, l1, 2);
    float inv0 = 1.0f / l0, inv1 = 1.0f / l1;

    int q = qrow0 + gid;
    size_t tk0 = (size_t)(b * SEQ + q) * DM + head * 64;
    size_t tk1 = tk0 + (size_t)8 * DM;
    #pragma unroll
    for (int od = 0; od < 8; od++){
        int d = od*8 + tig*2;
        *(uint32_t*)(Og + tk0 + d) = f22h(oacc[od][0] * inv0, oacc[od][1] * inv0);
        *(uint32_t*)(Og + tk1 + d) = f22h(oacc[od][2] * inv1, oacc[od][3] * inv1);
    }
}

// ---------------- launch ----------------
extern "C" void kernel_launch(void* const* d_in, const int* in_sizes, int n_in,
                              void* d_out, int out_size)
{
    const float* x  = (const float*)d_in[0];
    const float* Wq = (const float*)d_in[1];
    const float* Wk = (const float*)d_in[2];
    const float* Wv = (const float*)d_in[3];
    const float* Wo = (const float*)d_in[4];
    const float* g1 = (const float*)d_in[5];
    const float* g2 = (const float*)d_in[6];
    const float* W1 = (const float*)d_in[7];
    const float* W3 = (const float*)d_in[8];
    const float* W2 = (const float*)d_in[9];
    float* out = (float*)d_out;

    float *x1;
    __half *h1,*at,*h2,*gb,*w,*q,*k,*v;
    cudaGetSymbolAddress((void**)&x1, g_x1);
    cudaGetSymbolAddress((void**)&h1, g_h1);
    cudaGetSymbolAddress((void**)&at, g_at);
    cudaGetSymbolAddress((void**)&h2, g_h2);
    cudaGetSymbolAddress((void**)&gb, g_gb);
    cudaGetSymbolAddress((void**)&w,  g_w);
    cudaGetSymbolAddress((void**)&q,  g_q);
    cudaGetSymbolAddress((void**)&k,  g_k);
    cudaGetSymbolAddress((void**)&v,  g_v);

    cudaFuncSetAttribute(gemm_qkv, cudaFuncAttributeMaxDynamicSharedMemorySize, GH_SMEM);
    cudaFuncSetAttribute(gemm_add, cudaFuncAttributeMaxDynamicSharedMemorySize, GH_SMEM);
    cudaFuncSetAttribute(gemm_w13, cudaFuncAttributeMaxDynamicSharedMemorySize, W13_SMEM);
    cudaFuncSetAttribute(flash_tc, cudaFuncAttributeMaxDynamicSharedMemorySize, FA_SMEM);

    rope_table_k<<<SEQ * 32 / 256, 256>>>();
    cvt_all_k<<<4096, 256>>>(Wq, Wk, Wv, Wo, W1, W3, W2, w);

    rms_h_k<<<TOKENS, 256>>>(x, g1, h1);

    gemm_qkv<<<dim3(3*DM/64, TOKENS/128), 256, GH_SMEM>>>(h1, w, q, k, v);

    flash_tc<<<dim3(SEQ / 128, 2 * NH), 256, FA_SMEM>>>(q, k, v, at);

    gemm_add<<<dim3(DM/64, TOKENS/128), 256, GH_SMEM>>>(at, w + WOFF_O, x1, x, DM, DM);
    rms_h_k<<<TOKENS, 256>>>(x1, g2, h2);

    gemm_w13<<<dim3(DFF/64, TOKENS/128), 256, W13_SMEM>>>(h2, w + WOFF_1, w + WOFF_3, gb);
    gemm_add<<<dim3(DM/64, TOKENS/128), 256, GH_SMEM>>>(gb, w + WOFF_2, out, x1, DM, DFF);
}

// round 15
// speedup vs baseline: 1.0360x; 1.0174x over previous
#include <cuda_runtime.h>
#include <cuda_fp16.h>
#include <math.h>
#include <stdint.h>

#define TOKENS 4096
#define DM     1024
#define DFF    4096
#define SEQ    2048
#define NH     16
#define DK     64

// ---------------- scratch ----------------
__device__ float g_x1[TOKENS*DM];
__device__ float g_cs[SEQ*32];
__device__ float g_sn[SEQ*32];

__device__ __half g_h1[TOKENS*DM];
__device__ __half g_at[TOKENS*DM];
__device__ __half g_h2[TOKENS*DM];
__device__ __half g_gb[TOKENS*DFF];
__device__ __half g_q[TOKENS*DM];
__device__ __half g_k[TOKENS*DM];
__device__ __half g_v[TOKENS*DM];

#define WOFF_Q  0
#define WOFF_K  (1u<<20)
#define WOFF_V  (2u<<20)
#define WOFF_O  (3u<<20)
#define WOFF_1  (4u<<20)
#define WOFF_3  (8u<<20)
#define WOFF_2  (12u<<20)
__device__ __half g_w[16u<<20];

// ---------------- helpers ----------------
__device__ __forceinline__ uint32_t smem_u32(const void* p){
    uint32_t r;
    asm("{ .reg .u64 t; cvta.to.shared.u64 t, %1; cvt.u32.u64 %0, t; }" : "=r"(r) : "l"(p));
    return r;
}
__device__ __forceinline__ void cpa16(uint32_t dst, const void* src){
    asm volatile("cp.async.cg.shared.global [%0], [%1], 16;" :: "r"(dst), "l"(src) : "memory");
}
__device__ __forceinline__ void cp_commit(){ asm volatile("cp.async.commit_group;" ::: "memory"); }
__device__ __forceinline__ void cp_wait2(){ asm volatile("cp.async.wait_group 2;" ::: "memory"); }
__device__ __forceinline__ void cp_wait1(){ asm volatile("cp.async.wait_group 1;" ::: "memory"); }
__device__ __forceinline__ void cp_wait0(){ asm volatile("cp.async.wait_group 0;" ::: "memory"); }

__device__ __forceinline__ void ldsm4(uint32_t* r, uint32_t addr){
    asm volatile("ldmatrix.sync.aligned.m8n8.x4.shared.b16 {%0,%1,%2,%3}, [%4];"
        : "=r"(r[0]),"=r"(r[1]),"=r"(r[2]),"=r"(r[3]) : "r"(addr));
}
__device__ __forceinline__ void ldsm4t(uint32_t* r, uint32_t addr){
    asm volatile("ldmatrix.sync.aligned.m8n8.x4.trans.shared.b16 {%0,%1,%2,%3}, [%4];"
        : "=r"(r[0]),"=r"(r[1]),"=r"(r[2]),"=r"(r[3]) : "r"(addr));
}
__device__ __forceinline__ void mma16816(float* c, const uint32_t* a, uint32_t b0, uint32_t b1){
    asm volatile("mma.sync.aligned.m16n8k16.row.col.f32.f16.f16.f32 "
        "{%0,%1,%2,%3}, {%4,%5,%6,%7}, {%8,%9}, {%0,%1,%2,%3};"
        : "+f"(c[0]),"+f"(c[1]),"+f"(c[2]),"+f"(c[3])
        : "r"(a[0]),"r"(a[1]),"r"(a[2]),"r"(a[3]), "r"(b0),"r"(b1));
}
#define SW128(o) ((o) ^ (((o)>>3)&0x70))

__device__ __forceinline__ uint32_t f22h(float x, float y){
    __half2 h = __floats2half2_rn(x, y);
    return *reinterpret_cast<uint32_t*>(&h);
}

// ---------------- merged preamble: rope table + weight cvt + rmsnorm1 ----------------
// blocks [0,256): rope | [256,4352): cvt | [4352,8448): rms1
__global__ __launch_bounds__(256) void prep_k(
    const float* __restrict__ x,  const float* __restrict__ g1,
    const float* __restrict__ Wq, const float* __restrict__ Wk,
    const float* __restrict__ Wv, const float* __restrict__ Wo,
    const float* __restrict__ W1, const float* __restrict__ W3,
    const float* __restrict__ W2,
    __half* __restrict__ w, __half* __restrict__ h1out)
{
    int blk = blockIdx.x;
    int t   = threadIdx.x;
    if (blk < 256){
        // ---- RoPE table ----
        __shared__ float invf[32];
        if (t < 32) invf[t] = (float)pow(10000.0, -(double)(2 * t) / 64.0);
        __syncthreads();
        int i = blk * 256 + t;
        int pos = i >> 5;
        int j   = i & 31;
        float ang = (float)pos * invf[j];
        g_cs[i] = cosf(ang);
        g_sn[i] = sinf(ang);
    } else if (blk < 4352){
        // ---- weight fp32 -> fp16 ----
        int gb = blk - 256;
        const float* src; uint32_t woff; int lb;
        if (gb < 1024){
            int m = gb >> 8; lb = gb & 255;
            src = (m==0)?Wq:(m==1)?Wk:(m==2)?Wv:Wo;
            woff = (uint32_t)m << 20;
        } else if (gb < 2048){ src = W1; woff = WOFF_1; lb = gb - 1024; }
        else if (gb < 3072){ src = W3; woff = WOFF_3; lb = gb - 2048; }
        else               { src = W2; woff = WOFF_2; lb = gb - 3072; }
        uint2* hp = (uint2*)(w + woff);
        #pragma unroll
        for (int j = 0; j < 4; j++){
            int i4 = lb * 1024 + j * 256 + t;
            float4 v = ((const float4*)src)[i4];
            hp[i4] = make_uint2(f22h(v.x, v.y), f22h(v.z, v.w));
        }
    } else {
        // ---- rmsnorm(x, g1) -> fp16 ----
        int row = blk - 4352;
        const float4* xr = (const float4*)(x + (size_t)row * DM);
        float4 xv = xr[t];
        float ss = xv.x*xv.x + xv.y*xv.y + xv.z*xv.z + xv.w*xv.w;
        #pragma unroll
        for (int off = 16; off > 0; off >>= 1)
            ss += __shfl_xor_sync(0xffffffffu, ss, off);
        __shared__ float warpsum[8];
        if ((t & 31) == 0) warpsum[t >> 5] = ss;
        __syncthreads();
        float tot = warpsum[0]+warpsum[1]+warpsum[2]+warpsum[3]
                  + warpsum[4]+warpsum[5]+warpsum[6]+warpsum[7];
        float r = rsqrtf(tot * (1.0f / (float)DM) + 1e-5f);
        float4 gv = ((const float4*)g1)[t];
        size_t base4 = (size_t)row * (DM/4) + t;
        ((uint2*)h1out)[base4] = make_uint2(f22h(xv.x*r*gv.x, xv.y*r*gv.y),
                                            f22h(xv.z*r*gv.z, xv.w*r*gv.w));
    }
}

// ---------------- RMSNorm -> fp16 (second norm) ----------------
__global__ __launch_bounds__(256) void rms_h_k(const float* __restrict__ x,
                                               const float* __restrict__ g,
                                               __half* __restrict__ o) {
    int row = blockIdx.x;
    int t   = threadIdx.x;
    const float4* xr = (const float4*)(x + (size_t)row * DM);
    float4 xv = xr[t];
    float ss = xv.x*xv.x + xv.y*xv.y + xv.z*xv.z + xv.w*xv.w;
    #pragma unroll
    for (int off = 16; off > 0; off >>= 1)
        ss += __shfl_xor_sync(0xffffffffu, ss, off);
    __shared__ float warpsum[8];
    if ((t & 31) == 0) warpsum[t >> 5] = ss;
    __syncthreads();
    float tot = warpsum[0]+warpsum[1]+warpsum[2]+warpsum[3]
              + warpsum[4]+warpsum[5]+warpsum[6]+warpsum[7];
    float r = rsqrtf(tot * (1.0f / (float)DM) + 1e-5f);
    float4 gv = ((const float4*)g)[t];
    size_t base4 = (size_t)row * (DM/4) + t;
    ((uint2*)o)[base4] = make_uint2(f22h(xv.x*r*gv.x, xv.y*r*gv.y),
                                    f22h(xv.z*r*gv.z, xv.w*r*gv.w));
}

// =====================================================================
// fp16 GEMM engine: CTA 128x64, 256 thr (2 CTAs/SM), warp 4x2 of 32x32,
// BK=64, SW128 128B rows, 4-stage. Stage (24 KB): A@0(16K) B@16K(8K).
// =====================================================================
#define STGH     24576
#define GH_SMEM  (4*STGH)

__device__ __forceinline__ void gh_load(
    uint32_t tb, int tid, int m0, int n0, int kc, int K,
    const __half* A, const __half* B)
{
    int k0 = kc * 64;
    #pragma unroll
    for (int j = 0; j < 4; j++){
        int i = j * 256 + tid;
        int r = i >> 3, c16 = i & 7;
        cpa16(tb + SW128((uint32_t)(r << 7) + (c16 << 4)),
              A + (size_t)(m0 + r) * K + k0 + c16 * 8);
    }
    #pragma unroll
    for (int j = 0; j < 2; j++){
        int i = j * 256 + tid;
        int r = i >> 3, c16 = i & 7;
        cpa16(tb + 16384 + SW128((uint32_t)(r << 7) + (c16 << 4)),
              B + (size_t)(n0 + r) * K + k0 + c16 * 8);
    }
    cp_commit();
}

struct FragsH { uint32_t a[2][4], b[2][4]; };

__device__ __forceinline__ void gh_ldfrag(FragsH& f, uint32_t tb, int lane, int wm, int wn, int s){
    uint32_t colb = (uint32_t)(s*32) + ((lane >> 4) << 4);
    #pragma unroll
    for (int t = 0; t < 2; t++)
        ldsm4(f.a[t], tb + SW128((uint32_t)((wm*32 + t*16 + (lane & 15)) << 7) + colb));
    #pragma unroll
    for (int g = 0; g < 2; g++)
        ldsm4(f.b[g], tb + 16384 + SW128((uint32_t)((wn*32 + g*16 + (lane & 15)) << 7) + colb));
}

__device__ __forceinline__ void gh_mma(float acc[2][4][4], const FragsH& f){
    #pragma unroll
    for (int t = 0; t < 2; t++)
        #pragma unroll
        for (int g = 0; g < 2; g++)
            #pragma unroll
            for (int j = 0; j < 2; j++)
                mma16816(acc[t][g*2+j], f.a[t], f.b[g][j], f.b[g][j+2]);
}

__device__ __forceinline__ void gh_chunk(uint32_t tb, int lane, int wm, int wn, float acc[2][4][4]){
    FragsH f0, f1;
    gh_ldfrag(f0, tb, lane, wm, wn, 0);
    gh_ldfrag(f1, tb, lane, wm, wn, 1);
    gh_mma(acc, f0);
    gh_ldfrag(f0, tb, lane, wm, wn, 2);
    gh_mma(acc, f1);
    gh_ldfrag(f1, tb, lane, wm, wn, 3);
    gh_mma(acc, f0);
    gh_mma(acc, f1);
}

#define GH_MAIN(A_, B_, KDIM)                                                 \
    gh_load(sb, tid, m0, n0, 0, KDIM, A_, B_);                                \
    gh_load(sb + STGH, tid, m0, n0, 1, KDIM, A_, B_);                         \
    gh_load(sb + 2*STGH, tid, m0, n0, 2, KDIM, A_, B_);                       \
    for (int kc = 0; kc < NC; kc++){                                          \
        if (kc + 2 < NC) cp_wait2();                                          \
        else if (kc + 1 < NC) cp_wait1();                                     \
        else cp_wait0();                                                      \
        __syncthreads();                                                      \
        if (kc + 3 < NC)                                                      \
            gh_load(sb + ((kc+3)&3)*STGH, tid, m0, n0, kc+3, KDIM, A_, B_);   \
        gh_chunk(sb + (kc&3)*STGH, lane, wm, wn, acc);                        \
    }

// ---------------- fused QKV GEMM (N=3072) ----------------
__global__ __launch_bounds__(256, 2) void gemm_qkv(
    const __half* __restrict__ A, const __half* __restrict__ B,
    __half* __restrict__ Q, __half* __restrict__ K_, __half* __restrict__ V)
{
    extern __shared__ char smem[];
    uint32_t sb = smem_u32(smem);
    const int tid  = threadIdx.x;
    const int lane = tid & 31;
    const int wid  = tid >> 5;
    const int wm   = wid & 3;
    const int wn   = wid >> 2;
    const int m0 = blockIdx.y * 128, n0 = blockIdx.x * 64;
    const int NC = DM / 64;

    float acc[2][4][4];
    #pragma unroll
    for (int i = 0; i < 2; i++)
        #pragma unroll
        for (int j = 0; j < 4; j++)
            #pragma unroll
            for (int kk = 0; kk < 4; kk++) acc[i][j][kk] = 0.0f;

    GH_MAIN(A, B, DM)

    const int mtx = n0 >> 10;
    const float scl = (mtx == 0) ? 0.125f : 1.0f;
    __half* D = (mtx==0)?Q:(mtx==1)?K_:V;
    const int gid = lane >> 2, tig = lane & 3;
    #pragma unroll
    for (int tm = 0; tm < 2; tm++){
        #pragma unroll
        for (int half = 0; half < 2; half++){
            int m = m0 + wm*32 + tm*16 + gid + half*8;
            int pos = m & (SEQ - 1), b = m >> 11;
            #pragma unroll
            for (int tn = 0; tn < 4; tn++){
                int cc = (n0 & 1023) + wn*32 + tn*8 + tig*2;
                int head = cc >> 6, hi = cc & 63;
                size_t ob = ((size_t)(b * NH + head) * SEQ + pos) * DK + hi;
                float v0 = acc[tm][tn][half*2];
                float v1 = acc[tm][tn][half*2 + 1];
                float w0, w1;
                if (mtx < 2){
                    float cs = g_cs[pos * 32 + (hi >> 1)];
                    float sn = g_sn[pos * 32 + (hi >> 1)];
                    w0 = (v0 * cs - v1 * sn) * scl;
                    w1 = (v0 * sn + v1 * cs) * scl;
                } else { w0 = v0; w1 = v1; }
                *(uint32_t*)(D + ob) = f22h(w0, w1);
            }
        }
    }
}

// ---------------- GEMM + residual add (Wo, W2) ----------------
__global__ __launch_bounds__(256, 2) void gemm_add(
    const __half* __restrict__ A, const __half* __restrict__ B,
    float* __restrict__ C, const float* __restrict__ other, int N, int K)
{
    extern __shared__ char smem[];
    uint32_t sb = smem_u32(smem);
    const int tid  = threadIdx.x;
    const int lane = tid & 31;
    const int wid  = tid >> 5;
    const int wm   = wid & 3;
    const int wn   = wid >> 2;
    const int m0 = blockIdx.y * 128, n0 = blockIdx.x * 64;
    const int NC = K / 64;

    float acc[2][4][4];
    #pragma unroll
    for (int i = 0; i < 2; i++)
        #pragma unroll
        for (int j = 0; j < 4; j++)
            #pragma unroll
            for (int kk = 0; kk < 4; kk++) acc[i][j][kk] = 0.0f;

    GH_MAIN(A, B, K)

    const int gid = lane >> 2, tig = lane & 3;
    #pragma unroll
    for (int tm = 0; tm < 2; tm++){
        #pragma unroll
        for (int half = 0; half < 2; half++){
            int m = m0 + wm*32 + tm*16 + gid + half*8;
            #pragma unroll
            for (int tn = 0; tn < 4; tn++){
                int c = n0 + wn*32 + tn*8 + tig*2;
                size_t base = (size_t)m * N + c;
                C[base]     = other[base] + acc[tm][tn][half*2];
                C[base + 1] = other[base + 1] + acc[tm][tn][half*2 + 1];
            }
        }
    }
}

// ---------------- fused W1/W3 GEMM + silu(u)*v -> fp16 (3-stage) ----------------
#define W13_STG   32768
#define W13_SMEM  (3*W13_STG)

__global__ __launch_bounds__(256, 2) void gemm_w13(
    const __half* __restrict__ A,
    const __half* __restrict__ B1, const __half* __restrict__ B3,
    __half* __restrict__ Cg)
{
    extern __shared__ char smem[];
    uint32_t sb = smem_u32(smem);
    const int tid  = threadIdx.x;
    const int lane = tid & 31;
    const int wid  = tid >> 5;
    const int wm   = wid & 3;
    const int wn   = wid >> 2;
    const int m0 = blockIdx.y * 128, n0 = blockIdx.x * 64;
    const int NC = DM / 64;
    const int K  = DM;

    float accU[2][4][4], accV[2][4][4];
    #pragma unroll
    for (int i = 0; i < 2; i++)
        #pragma unroll
        for (int j = 0; j < 4; j++)
            #pragma unroll
            for (int kk = 0; kk < 4; kk++){ accU[i][j][kk] = 0.0f; accV[i][j][kk] = 0.0f; }

    auto load_chunk = [&](int kc, int stage){
        uint32_t tb = sb + stage * W13_STG;
        int k0 = kc * 64;
        #pragma unroll
        for (int j = 0; j < 4; j++){
            int i = j * 256 + tid;
            int r = i >> 3, c16 = i & 7;
            cpa16(tb + SW128((uint32_t)(r << 7) + (c16 << 4)),
                  A + (size_t)(m0 + r) * K + k0 + c16 * 8);
        }
        #pragma unroll
        for (int j = 0; j < 2; j++){
            int i = j * 256 + tid;
            int r = i >> 3, c16 = i & 7;
            uint32_t o = SW128((uint32_t)(r << 7) + (c16 << 4));
            cpa16(tb + 16384 + o, B1 + (size_t)(n0 + r) * K + k0 + c16 * 8);
            cpa16(tb + 24576 + o, B3 + (size_t)(n0 + r) * K + k0 + c16 * 8);
        }
        cp_commit();
    };

    load_chunk(0, 0);
    load_chunk(1, 1);

    for (int kc = 0; kc < NC; kc++){
        if (kc + 1 < NC) cp_wait1(); else cp_wait0();
        __syncthreads();
        if (kc + 2 < NC) load_chunk(kc + 2, (kc + 2) % 3);
        uint32_t tb = sb + (kc % 3) * W13_STG;

        #pragma unroll
        for (int s = 0; s < 4; s++){
            uint32_t colb = (uint32_t)(s*32) + ((lane >> 4) << 4);
            uint32_t a[2][4], b1[2][4], b3[2][4];
            #pragma unroll
            for (int t = 0; t < 2; t++)
                ldsm4(a[t], tb + SW128((uint32_t)((wm*32 + t*16 + (lane & 15)) << 7) + colb));
            #pragma unroll
            for (int g = 0; g < 2; g++){
                uint32_t so = SW128((uint32_t)((wn*32 + g*16 + (lane & 15)) << 7) + colb);
                ldsm4(b1[g], tb + 16384 + so);
                ldsm4(b3[g], tb + 24576 + so);
            }
            #pragma unroll
            for (int t = 0; t < 2; t++)
                #pragma unroll
                for (int g = 0; g < 2; g++)
                    #pragma unroll
                    for (int j = 0; j < 2; j++){
                        mma16816(accU[t][g*2+j], a[t], b1[g][j], b1[g][j+2]);
                        mma16816(accV[t][g*2+j], a[t], b3[g][j], b3[g][j+2]);
                    }
        }
    }

    const int gid = lane >> 2, tig = lane & 3;
    #pragma unroll
    for (int tm = 0; tm < 2; tm++){
        #pragma unroll
        for (int half = 0; half < 2; half++){
            int m = m0 + wm*32 + tm*16 + gid + half*8;
            #pragma unroll
            for (int tn = 0; tn < 4; tn++){
                int c = n0 + wn*32 + tn*8 + tig*2;
                size_t base = (size_t)m * DFF + c;
                float u0 = accU[tm][tn][half*2], u1 = accU[tm][tn][half*2+1];
                float v0 = accV[tm][tn][half*2], v1 = accV[tm][tn][half*2+1];
                float w0 = v0 * u0 / (1.0f + __expf(-u0));
                float w1 = v1 * u1 / (1.0f + __expf(-u1));
                *(uint32_t*)(Cg + base) = f22h(w0, w1);
            }
        }
    }
}

// ---------------- fp16 flash attention (causal) ----------------
#define FA_SMEM (16384 + 3*16384)

__global__ __launch_bounds__(256, 2) void flash_tc(
    const __half* __restrict__ Qg, const __half* __restrict__ Kg,
    const __half* __restrict__ Vg, __half* __restrict__ Og)
{
    extern __shared__ char smem[];
    uint32_t sb = smem_u32(smem);
    const int tid  = threadIdx.x;
    const int lane = tid & 31;
    const int w    = tid >> 5;
    const int gid  = lane >> 2, tig = lane & 3;
    const int qt   = (int)gridDim.x - 1 - (int)blockIdx.x;
    const int bh   = blockIdx.y;
    const int b    = bh >> 4, head = bh & 15;
    const size_t base = (size_t)bh * SEQ * DK;
    const int q0 = qt * 128;
    const int NT = 2 * qt + 2;

    #pragma unroll
    for (int j = 0; j < 4; j++){
        int i = j * 256 + tid;
        int r = i >> 3, c16 = i & 7;
        cpa16(sb + SW128((uint32_t)(r << 7) + (c16 << 4)),
              Qg + base + (size_t)(q0 + r) * DK + c16 * 8);
    }
    cp_commit();

    auto load_kv = [&](int kt, int stage){
        uint32_t tb = sb + 16384 + stage * 16384;
        size_t kb = base + (size_t)kt * 64 * DK;
        #pragma unroll
        for (int j = 0; j < 2; j++){
            int i = j * 256 + tid;
            int r = i >> 3, c16 = i & 7;
            uint32_t o = SW128((uint32_t)(r << 7) + (c16 << 4));
            cpa16(tb + o,        Kg + kb + (size_t)r * DK + c16 * 8);
            cpa16(tb + 8192 + o, Vg + kb + (size_t)r * DK + c16 * 8);
        }
        cp_commit();
    };
    load_kv(0, 0);
    load_kv(1, 1);

    cp_wait2();
    __syncthreads();

    uint32_t qf[4][4];
    #pragma unroll
    for (int s = 0; s < 4; s++){
        uint32_t o = (uint32_t)((w*16 + (lane & 15)) << 7) + s*32 + ((lane >> 4) << 4);
        ldsm4(qf[s], sb + SW128(o));
    }

    float oacc[8][4];
    #pragma unroll
    for (int i = 0; i < 8; i++)
        #pragma unroll
        for (int j = 0; j < 4; j++) oacc[i][j] = 0.0f;
    float m0 = -1e30f, m1 = -1e30f, l0 = 0.0f, l1 = 0.0f;
    const int qrow0 = q0 + w * 16;

    for (int kt = 0; kt < NT; kt++){
        if (kt + 1 < NT) cp_wait1(); else cp_wait0();
        __syncthreads();
        uint32_t tb = sb + 16384 + (kt % 3) * 16384;

        float sc[8][4];
        #pragma unroll
        for (int i = 0; i < 8; i++)
            #pragma unroll
            for (int j = 0; j < 4; j++) sc[i][j] = 0.0f;

        #pragma unroll
        for (int s = 0; s < 4; s++){
            uint32_t kf[4][4];
            #pragma unroll
            for (int g = 0; g < 4; g++){
                uint32_t o = (uint32_t)((g*16 + (lane & 15)) << 7) + s*32 + ((lane >> 4) << 4);
                ldsm4(kf[g], tb + SW128(o));
            }
            #pragma unroll
            for (int g = 0; g < 4; g++)
                #pragma unroll
                for (int j = 0; j < 2; j++)
                    mma16816(sc[g*2+j], qf[s], kf[g][j], kf[g][j+2]);
        }

        if (kt*64 + 63 > qrow0){
            int r0 = qrow0 + gid, r1 = r0 + 8;
            #pragma unroll
            for (int tn = 0; tn < 8; tn++){
                int key = kt*64 + tn*8 + tig*2;
                if (key     > r0) sc[tn][0] = -1e9f;
                if (key + 1 > r0) sc[tn][1] = -1e9f;
                if (key     > r1) sc[tn][2] = -1e9f;
                if (key + 1 > r1) sc[tn][3] = -1e9f;
            }
        }

        float t0 = -1e30f, t1 = -1e30f;
        #pragma unroll
        for (int tn = 0; tn < 8; tn++){
            t0 = fmaxf(t0, fmaxf(sc[tn][0], sc[tn][1]));
            t1 = fmaxf(t1, fmaxf(sc[tn][2], sc[tn][3]));
        }
        t0 = fmaxf(t0, __shfl_xor_sync(0xffffffffu, t0, 1));
        t0 = fmaxf(t0, __shfl_xor_sync(0xffffffffu, t0, 2));
        t1 = fmaxf(t1, __shfl_xor_sync(0xffffffffu, t1, 1));
        t1 = fmaxf(t1, __shfl_xor_sync(0xffffffffu, t1, 2));
        float nm0 = fmaxf(m0, t0), nm1 = fmaxf(m1, t1);
        float c0 = __expf(m0 - nm0), c1 = __expf(m1 - nm1);
        l0 *= c0; l1 *= c1;
        #pragma unroll
        for (int tn = 0; tn < 8; tn++){
            sc[tn][0] = __expf(sc[tn][0] - nm0);
            sc[tn][1] = __expf(sc[tn][1] - nm0);
            sc[tn][2] = __expf(sc[tn][2] - nm1);
            sc[tn][3] = __expf(sc[tn][3] - nm1);
            l0 += sc[tn][0] + sc[tn][1];
            l1 += sc[tn][2] + sc[tn][3];
        }
        #pragma unroll
        for (int od = 0; od < 8; od++){
            oacc[od][0] *= c0; oacc[od][1] *= c0;
            oacc[od][2] *= c1; oacc[od][3] *= c1;
        }
        m0 = nm0; m1 = nm1;

        uint32_t pf[4][4];
        #pragma unroll
        for (int s = 0; s < 4; s++){
            pf[s][0] = f22h(sc[2*s][0],   sc[2*s][1]);
            pf[s][1] = f22h(sc[2*s][2],   sc[2*s][3]);
            pf[s][2] = f22h(sc[2*s+1][0], sc[2*s+1][1]);
            pf[s][3] = f22h(sc[2*s+1][2], sc[2*s+1][3]);
        }

        #pragma unroll
        for (int s = 0; s < 4; s++){
            uint32_t vf[4][4];
            #pragma unroll
            for (int gd = 0; gd < 4; gd++){
                uint32_t row = s*16 + (lane & 7) + ((lane & 16) >> 1);
                uint32_t col = gd*16 + (lane & 8);
                ldsm4t(vf[gd], tb + 8192 + SW128((row << 7) + (col << 1)));
            }
            #pragma unroll
            for (int gd = 0; gd < 4; gd++)
                #pragma unroll
                for (int j = 0; j < 2; j++)
                    mma16816(oacc[gd*2+j], pf[s], vf[gd][j], vf[gd][j+2]);
        }

        if (kt + 2 < NT) load_kv(kt + 2, (kt + 2) % 3);
    }

    l0 += __shfl_xor_sync(0xffffffffu, l0, 1);
    l0 += __shfl_xor_sync(0xffffffffu, l0, 2);
    l1 += __shfl_xor_sync(0xffffffffu, l1, 1);
    l1 += __shfl_xor_sync(0xffffffffu, l1, 2);
    float inv0 = 1.0f / l0, inv1 = 1.0f / l1;

    int q = qrow0 + gid;
    size_t tk0 = (size_t)(b * SEQ + q) * DM + head * 64;
    size_t tk1 = tk0 + (size_t)8 * DM;
    #pragma unroll
    for (int od = 0; od < 8; od++){
        int d = od*8 + tig*2;
        *(uint32_t*)(Og + tk0 + d) = f22h(oacc[od][0] * inv0, oacc[od][1] * inv0);
        *(uint32_t*)(Og + tk1 + d) = f22h(oacc[od][2] * inv1, oacc[od][3] * inv1);
    }
}

// ---------------- launch ----------------
extern "C" void kernel_launch(void* const* d_in, const int* in_sizes, int n_in,
                              void* d_out, int out_size)
{
    const float* x  = (const float*)d_in[0];
    const float* Wq = (const float*)d_in[1];
    const float* Wk = (const float*)d_in[2];
    const float* Wv = (const float*)d_in[3];
    const float* Wo = (const float*)d_in[4];
    const float* g1 = (const float*)d_in[5];
    const float* g2 = (const float*)d_in[6];
    const float* W1 = (const float*)d_in[7];
    const float* W3 = (const float*)d_in[8];
    const float* W2 = (const float*)d_in[9];
    float* out = (float*)d_out;

    float *x1;
    __half *h1,*at,*h2,*gb,*w,*q,*k,*v;
    cudaGetSymbolAddress((void**)&x1, g_x1);
    cudaGetSymbolAddress((void**)&h1, g_h1);
    cudaGetSymbolAddress((void**)&at, g_at);
    cudaGetSymbolAddress((void**)&h2, g_h2);
    cudaGetSymbolAddress((void**)&gb, g_gb);
    cudaGetSymbolAddress((void**)&w,  g_w);
    cudaGetSymbolAddress((void**)&q,  g_q);
    cudaGetSymbolAddress((void**)&k,  g_k);
    cudaGetSymbolAddress((void**)&v,  g_v);

    cudaFuncSetAttribute(gemm_qkv, cudaFuncAttributeMaxDynamicSharedMemorySize, GH_SMEM);
    cudaFuncSetAttribute(gemm_add, cudaFuncAttributeMaxDynamicSharedMemorySize, GH_SMEM);
    cudaFuncSetAttribute(gemm_w13, cudaFuncAttributeMaxDynamicSharedMemorySize, W13_SMEM);
    cudaFuncSetAttribute(flash_tc, cudaFuncAttributeMaxDynamicSharedMemorySize, FA_SMEM);

    prep_k<<<8448, 256>>>(x, g1, Wq, Wk, Wv, Wo, W1, W3, W2, w, h1);

    gemm_qkv<<<dim3(3*DM/64, TOKENS/128), 256, GH_SMEM>>>(h1, w, q, k, v);

    flash_tc<<<dim3(SEQ / 128, 2 * NH), 256, FA_SMEM>>>(q, k, v, at);

    gemm_add<<<dim3(DM/64, TOKENS/128), 256, GH_SMEM>>>(at, w + WOFF_O, x1, x, DM, DM);
    rms_h_k<<<TOKENS, 256>>>(x1, g2, h2);

    gemm_w13<<<dim3(DFF/64, TOKENS/128), 256, W13_SMEM>>>(h2, w + WOFF_1, w + WOFF_3, gb);
    gemm_add<<<dim3(DM/64, TOKENS/128), 256, GH_SMEM>>>(gb, w + WOFF_2, out, x1, DM, DFF);
}

// round 16
// speedup vs baseline: 1.0485x; 1.0121x over previous
#include <cuda_runtime.h>
#include <cuda_fp16.h>
#include <math.h>
#include <stdint.h>

#define TOKENS 4096
#define DM     1024
#define DFF    4096
#define SEQ    2048
#define NH     16
#define DK     64

// ---------------- scratch ----------------
__device__ float g_x1[TOKENS*DM];
__device__ float g_cs[SEQ*32];
__device__ float g_sn[SEQ*32];

__device__ __half g_h1[TOKENS*DM];
__device__ __half g_at[TOKENS*DM];
__device__ __half g_h2[TOKENS*DM];
__device__ __half g_gb[TOKENS*DFF];
__device__ __half g_q[TOKENS*DM];
__device__ __half g_k[TOKENS*DM];
__device__ __half g_v[TOKENS*DM];

#define WOFF_Q  0
#define WOFF_K  (1u<<20)
#define WOFF_V  (2u<<20)
#define WOFF_O  (3u<<20)
#define WOFF_1  (4u<<20)
#define WOFF_3  (8u<<20)
#define WOFF_2  (12u<<20)
__device__ __half g_w[16u<<20];

// ---------------- helpers ----------------
__device__ __forceinline__ uint32_t smem_u32(const void* p){
    uint32_t r;
    asm("{ .reg .u64 t; cvta.to.shared.u64 t, %1; cvt.u32.u64 %0, t; }" : "=r"(r) : "l"(p));
    return r;
}
__device__ __forceinline__ void cpa16(uint32_t dst, const void* src){
    asm volatile("cp.async.cg.shared.global [%0], [%1], 16;" :: "r"(dst), "l"(src) : "memory");
}
__device__ __forceinline__ void cp_commit(){ asm volatile("cp.async.commit_group;" ::: "memory"); }
__device__ __forceinline__ void cp_wait2(){ asm volatile("cp.async.wait_group 2;" ::: "memory"); }
__device__ __forceinline__ void cp_wait1(){ asm volatile("cp.async.wait_group 1;" ::: "memory"); }
__device__ __forceinline__ void cp_wait0(){ asm volatile("cp.async.wait_group 0;" ::: "memory"); }

__device__ __forceinline__ void ldsm4(uint32_t* r, uint32_t addr){
    asm volatile("ldmatrix.sync.aligned.m8n8.x4.shared.b16 {%0,%1,%2,%3}, [%4];"
        : "=r"(r[0]),"=r"(r[1]),"=r"(r[2]),"=r"(r[3]) : "r"(addr));
}
__device__ __forceinline__ void ldsm4t(uint32_t* r, uint32_t addr){
    asm volatile("ldmatrix.sync.aligned.m8n8.x4.trans.shared.b16 {%0,%1,%2,%3}, [%4];"
        : "=r"(r[0]),"=r"(r[1]),"=r"(r[2]),"=r"(r[3]) : "r"(addr));
}
__device__ __forceinline__ void mma16816(float* c, const uint32_t* a, uint32_t b0, uint32_t b1){
    asm volatile("mma.sync.aligned.m16n8k16.row.col.f32.f16.f16.f32 "
        "{%0,%1,%2,%3}, {%4,%5,%6,%7}, {%8,%9}, {%0,%1,%2,%3};"
        : "+f"(c[0]),"+f"(c[1]),"+f"(c[2]),"+f"(c[3])
        : "r"(a[0]),"r"(a[1]),"r"(a[2]),"r"(a[3]), "r"(b0),"r"(b1));
}
#define SW128(o) ((o) ^ (((o)>>3)&0x70))

__device__ __forceinline__ uint32_t f22h(float x, float y){
    __half2 h = __floats2half2_rn(x, y);
    return *reinterpret_cast<uint32_t*>(&h);
}

// ---------------- merged preamble: rope table + weight cvt + rmsnorm1 ----------------
// blocks [0,256): rope | [256,2304): cvt (8 float4/thread, MLP=8) | [2304,6400): rms1
__global__ __launch_bounds__(256) void prep_k(
    const float* __restrict__ x,  const float* __restrict__ g1,
    const float* __restrict__ Wq, const float* __restrict__ Wk,
    const float* __restrict__ Wv, const float* __restrict__ Wo,
    const float* __restrict__ W1, const float* __restrict__ W3,
    const float* __restrict__ W2,
    __half* __restrict__ w, __half* __restrict__ h1out)
{
    int blk = blockIdx.x;
    int t   = threadIdx.x;
    if (blk < 256){
        // ---- RoPE table ----
        __shared__ float invf[32];
        if (t < 32) invf[t] = (float)pow(10000.0, -(double)(2 * t) / 64.0);
        __syncthreads();
        int i = blk * 256 + t;
        int pos = i >> 5;
        int j   = i & 31;
        float ang = (float)pos * invf[j];
        g_cs[i] = cosf(ang);
        g_sn[i] = sinf(ang);
    } else if (blk < 2304){
        // ---- weight fp32 -> fp16, batched loads ----
        int gb = blk - 256;                 // 0..2047
        const float* src; uint32_t woff; int lb;
        if (gb < 512){
            int m = gb >> 7; lb = gb & 127;
            src = (m==0)?Wq:(m==1)?Wk:(m==2)?Wv:Wo;
            woff = (uint32_t)m << 20;
        } else if (gb < 1024){ src = W1; woff = WOFF_1; lb = gb - 512; }
        else if (gb < 1536){ src = W3; woff = WOFF_3; lb = gb - 1024; }
        else               { src = W2; woff = WOFF_2; lb = gb - 1536; }
        const float4* sp = (const float4*)src;
        float4 v[8];
        #pragma unroll
        for (int j = 0; j < 8; j++)
            v[j] = __ldcs(&sp[lb * 2048 + j * 256 + t]);
        uint2* hp = (uint2*)(w + woff);
        #pragma unroll
        for (int j = 0; j < 8; j++){
            int i4 = lb * 2048 + j * 256 + t;
            hp[i4] = make_uint2(f22h(v[j].x, v[j].y), f22h(v[j].z, v[j].w));
        }
    } else {
        // ---- rmsnorm(x, g1) -> fp16 ----
        int row = blk - 2304;
        const float4* xr = (const float4*)(x + (size_t)row * DM);
        float4 xv = xr[t];
        float ss = xv.x*xv.x + xv.y*xv.y + xv.z*xv.z + xv.w*xv.w;
        #pragma unroll
        for (int off = 16; off > 0; off >>= 1)
            ss += __shfl_xor_sync(0xffffffffu, ss, off);
        __shared__ float warpsum[8];
        if ((t & 31) == 0) warpsum[t >> 5] = ss;
        __syncthreads();
        float tot = warpsum[0]+warpsum[1]+warpsum[2]+warpsum[3]
                  + warpsum[4]+warpsum[5]+warpsum[6]+warpsum[7];
        float r = rsqrtf(tot * (1.0f / (float)DM) + 1e-5f);
        float4 gv = ((const float4*)g1)[t];
        size_t base4 = (size_t)row * (DM/4) + t;
        ((uint2*)h1out)[base4] = make_uint2(f22h(xv.x*r*gv.x, xv.y*r*gv.y),
                                            f22h(xv.z*r*gv.z, xv.w*r*gv.w));
    }
}

// ---------------- RMSNorm -> fp16 (second norm) ----------------
__global__ __launch_bounds__(256) void rms_h_k(const float* __restrict__ x,
                                               const float* __restrict__ g,
                                               __half* __restrict__ o) {
    int row = blockIdx.x;
    int t   = threadIdx.x;
    const float4* xr = (const float4*)(x + (size_t)row * DM);
    float4 xv = xr[t];
    float ss = xv.x*xv.x + xv.y*xv.y + xv.z*xv.z + xv.w*xv.w;
    #pragma unroll
    for (int off = 16; off > 0; off >>= 1)
        ss += __shfl_xor_sync(0xffffffffu, ss, off);
    __shared__ float warpsum[8];
    if ((t & 31) == 0) warpsum[t >> 5] = ss;
    __syncthreads();
    float tot = warpsum[0]+warpsum[1]+warpsum[2]+warpsum[3]
              + warpsum[4]+warpsum[5]+warpsum[6]+warpsum[7];
    float r = rsqrtf(tot * (1.0f / (float)DM) + 1e-5f);
    float4 gv = ((const float4*)g)[t];
    size_t base4 = (size_t)row * (DM/4) + t;
    ((uint2*)o)[base4] = make_uint2(f22h(xv.x*r*gv.x, xv.y*r*gv.y),
                                    f22h(xv.z*r*gv.z, xv.w*r*gv.w));
}

// =====================================================================
// fp16 GEMM engine: CTA 128x64, 256 thr (2 CTAs/SM), warp 4x2 of 32x32,
// BK=64, SW128 128B rows, 4-stage. Stage (24 KB): A@0(16K) B@16K(8K).
// =====================================================================
#define STGH     24576
#define GH_SMEM  (4*STGH)

__device__ __forceinline__ void gh_load(
    uint32_t tb, int tid, int m0, int n0, int kc, int K,
    const __half* A, const __half* B)
{
    int k0 = kc * 64;
    #pragma unroll
    for (int j = 0; j < 4; j++){
        int i = j * 256 + tid;
        int r = i >> 3, c16 = i & 7;
        cpa16(tb + SW128((uint32_t)(r << 7) + (c16 << 4)),
              A + (size_t)(m0 + r) * K + k0 + c16 * 8);
    }
    #pragma unroll
    for (int j = 0; j < 2; j++){
        int i = j * 256 + tid;
        int r = i >> 3, c16 = i & 7;
        cpa16(tb + 16384 + SW128((uint32_t)(r << 7) + (c16 << 4)),
              B + (size_t)(n0 + r) * K + k0 + c16 * 8);
    }
    cp_commit();
}

struct FragsH { uint32_t a[2][4], b[2][4]; };

__device__ __forceinline__ void gh_ldfrag(FragsH& f, uint32_t tb, int lane, int wm, int wn, int s){
    uint32_t colb = (uint32_t)(s*32) + ((lane >> 4) << 4);
    #pragma unroll
    for (int t = 0; t < 2; t++)
        ldsm4(f.a[t], tb + SW128((uint32_t)((wm*32 + t*16 + (lane & 15)) << 7) + colb));
    #pragma unroll
    for (int g = 0; g < 2; g++)
        ldsm4(f.b[g], tb + 16384 + SW128((uint32_t)((wn*32 + g*16 + (lane & 15)) << 7) + colb));
}

__device__ __forceinline__ void gh_mma(float acc[2][4][4], const FragsH& f){
    #pragma unroll
    for (int t = 0; t < 2; t++)
        #pragma unroll
        for (int g = 0; g < 2; g++)
            #pragma unroll
            for (int j = 0; j < 2; j++)
                mma16816(acc[t][g*2+j], f.a[t], f.b[g][j], f.b[g][j+2]);
}

__device__ __forceinline__ void gh_chunk(uint32_t tb, int lane, int wm, int wn, float acc[2][4][4]){
    FragsH f0, f1;
    gh_ldfrag(f0, tb, lane, wm, wn, 0);
    gh_ldfrag(f1, tb, lane, wm, wn, 1);
    gh_mma(acc, f0);
    gh_ldfrag(f0, tb, lane, wm, wn, 2);
    gh_mma(acc, f1);
    gh_ldfrag(f1, tb, lane, wm, wn, 3);
    gh_mma(acc, f0);
    gh_mma(acc, f1);
}

#define GH_MAIN(A_, B_, KDIM)                                                 \
    gh_load(sb, tid, m0, n0, 0, KDIM, A_, B_);                                \
    gh_load(sb + STGH, tid, m0, n0, 1, KDIM, A_, B_);                         \
    gh_load(sb + 2*STGH, tid, m0, n0, 2, KDIM, A_, B_);                       \
    for (int kc = 0; kc < NC; kc++){                                          \
        if (kc + 2 < NC) cp_wait2();                                          \
        else if (kc + 1 < NC) cp_wait1();                                     \
        else cp_wait0();                                                      \
        __syncthreads();                                                      \
        if (kc + 3 < NC)                                                      \
            gh_load(sb + ((kc+3)&3)*STGH, tid, m0, n0, kc+3, KDIM, A_, B_);   \
        gh_chunk(sb + (kc&3)*STGH, lane, wm, wn, acc);                        \
    }

// ---------------- fused QKV GEMM (N=3072) ----------------
__global__ __launch_bounds__(256, 2) void gemm_qkv(
    const __half* __restrict__ A, const __half* __restrict__ B,
    __half* __restrict__ Q, __half* __restrict__ K_, __half* __restrict__ V)
{
    extern __shared__ char smem[];
    uint32_t sb = smem_u32(smem);
    const int tid  = threadIdx.x;
    const int lane = tid & 31;
    const int wid  = tid >> 5;
    const int wm   = wid & 3;
    const int wn   = wid >> 2;
    const int m0 = blockIdx.y * 128, n0 = blockIdx.x * 64;
    const int NC = DM / 64;

    float acc[2][4][4];
    #pragma unroll
    for (int i = 0; i < 2; i++)
        #pragma unroll
        for (int j = 0; j < 4; j++)
            #pragma unroll
            for (int kk = 0; kk < 4; kk++) acc[i][j][kk] = 0.0f;

    GH_MAIN(A, B, DM)

    const int mtx = n0 >> 10;
    const float scl = (mtx == 0) ? 0.125f : 1.0f;
    __half* D = (mtx==0)?Q:(mtx==1)?K_:V;
    const int gid = lane >> 2, tig = lane & 3;
    #pragma unroll
    for (int tm = 0; tm < 2; tm++){
        #pragma unroll
        for (int half = 0; half < 2; half++){
            int m = m0 + wm*32 + tm*16 + gid + half*8;
            int pos = m & (SEQ - 1), b = m >> 11;
            #pragma unroll
            for (int tn = 0; tn < 4; tn++){
                int cc = (n0 & 1023) + wn*32 + tn*8 + tig*2;
                int head = cc >> 6, hi = cc & 63;
                size_t ob = ((size_t)(b * NH + head) * SEQ + pos) * DK + hi;
                float v0 = acc[tm][tn][half*2];
                float v1 = acc[tm][tn][half*2 + 1];
                float w0, w1;
                if (mtx < 2){
                    float cs = g_cs[pos * 32 + (hi >> 1)];
                    float sn = g_sn[pos * 32 + (hi >> 1)];
                    w0 = (v0 * cs - v1 * sn) * scl;
                    w1 = (v0 * sn + v1 * cs) * scl;
                } else { w0 = v0; w1 = v1; }
                *(uint32_t*)(D + ob) = f22h(w0, w1);
            }
        }
    }
}

// ---------------- GEMM + residual add (Wo, W2) ----------------
__global__ __launch_bounds__(256, 2) void gemm_add(
    const __half* __restrict__ A, const __half* __restrict__ B,
    float* __restrict__ C, const float* __restrict__ other, int N, int K)
{
    extern __shared__ char smem[];
    uint32_t sb = smem_u32(smem);
    const int tid  = threadIdx.x;
    const int lane = tid & 31;
    const int wid  = tid >> 5;
    const int wm   = wid & 3;
    const int wn   = wid >> 2;
    const int m0 = blockIdx.y * 128, n0 = blockIdx.x * 64;
    const int NC = K / 64;

    float acc[2][4][4];
    #pragma unroll
    for (int i = 0; i < 2; i++)
        #pragma unroll
        for (int j = 0; j < 4; j++)
            #pragma unroll
            for (int kk = 0; kk < 4; kk++) acc[i][j][kk] = 0.0f;

    GH_MAIN(A, B, K)

    const int gid = lane >> 2, tig = lane & 3;
    #pragma unroll
    for (int tm = 0; tm < 2; tm++){
        #pragma unroll
        for (int half = 0; half < 2; half++){
            int m = m0 + wm*32 + tm*16 + gid + half*8;
            #pragma unroll
            for (int tn = 0; tn < 4; tn++){
                int c = n0 + wn*32 + tn*8 + tig*2;
                size_t base = (size_t)m * N + c;
                float2 o2 = *(const float2*)(other + base);
                float2 r2 = make_float2(o2.x + acc[tm][tn][half*2],
                                        o2.y + acc[tm][tn][half*2 + 1]);
                *(float2*)(C + base) = r2;
            }
        }
    }
}

// ---------------- fused W1/W3 GEMM + silu(u)*v -> fp16 (3-stage) ----------------
#define W13_STG   32768
#define W13_SMEM  (3*W13_STG)

__global__ __launch_bounds__(256, 2) void gemm_w13(
    const __half* __restrict__ A,
    const __half* __restrict__ B1, const __half* __restrict__ B3,
    __half* __restrict__ Cg)
{
    extern __shared__ char smem[];
    uint32_t sb = smem_u32(smem);
    const int tid  = threadIdx.x;
    const int lane = tid & 31;
    const int wid  = tid >> 5;
    const int wm   = wid & 3;
    const int wn   = wid >> 2;
    const int m0 = blockIdx.y * 128, n0 = blockIdx.x * 64;
    const int NC = DM / 64;
    const int K  = DM;

    float accU[2][4][4], accV[2][4][4];
    #pragma unroll
    for (int i = 0; i < 2; i++)
        #pragma unroll
        for (int j = 0; j < 4; j++)
            #pragma unroll
            for (int kk = 0; kk < 4; kk++){ accU[i][j][kk] = 0.0f; accV[i][j][kk] = 0.0f; }

    auto load_chunk = [&](int kc, int stage){
        uint32_t tb = sb + stage * W13_STG;
        int k0 = kc * 64;
        #pragma unroll
        for (int j = 0; j < 4; j++){
            int i = j * 256 + tid;
            int r = i >> 3, c16 = i & 7;
            cpa16(tb + SW128((uint32_t)(r << 7) + (c16 << 4)),
                  A + (size_t)(m0 + r) * K + k0 + c16 * 8);
        }
        #pragma unroll
        for (int j = 0; j < 2; j++){
            int i = j * 256 + tid;
            int r = i >> 3, c16 = i & 7;
            uint32_t o = SW128((uint32_t)(r << 7) + (c16 << 4));
            cpa16(tb + 16384 + o, B1 + (size_t)(n0 + r) * K + k0 + c16 * 8);
            cpa16(tb + 24576 + o, B3 + (size_t)(n0 + r) * K + k0 + c16 * 8);
        }
        cp_commit();
    };

    load_chunk(0, 0);
    load_chunk(1, 1);

    for (int kc = 0; kc < NC; kc++){
        if (kc + 1 < NC) cp_wait1(); else cp_wait0();
        __syncthreads();
        if (kc + 2 < NC) load_chunk(kc + 2, (kc + 2) % 3);
        uint32_t tb = sb + (kc % 3) * W13_STG;

        #pragma unroll
        for (int s = 0; s < 4; s++){
            uint32_t colb = (uint32_t)(s*32) + ((lane >> 4) << 4);
            uint32_t a[2][4], b1[2][4], b3[2][4];
            #pragma unroll
            for (int t = 0; t < 2; t++)
                ldsm4(a[t], tb + SW128((uint32_t)((wm*32 + t*16 + (lane & 15)) << 7) + colb));
            #pragma unroll
            for (int g = 0; g < 2; g++){
                uint32_t so = SW128((uint32_t)((wn*32 + g*16 + (lane & 15)) << 7) + colb);
                ldsm4(b1[g], tb + 16384 + so);
                ldsm4(b3[g], tb + 24576 + so);
            }
            #pragma unroll
            for (int t = 0; t < 2; t++)
                #pragma unroll
                for (int g = 0; g < 2; g++)
                    #pragma unroll
                    for (int j = 0; j < 2; j++){
                        mma16816(accU[t][g*2+j], a[t], b1[g][j], b1[g][j+2]);
                        mma16816(accV[t][g*2+j], a[t], b3[g][j], b3[g][j+2]);
                    }
        }
    }

    const int gid = lane >> 2, tig = lane & 3;
    #pragma unroll
    for (int tm = 0; tm < 2; tm++){
        #pragma unroll
        for (int half = 0; half < 2; half++){
            int m = m0 + wm*32 + tm*16 + gid + half*8;
            #pragma unroll
            for (int tn = 0; tn < 4; tn++){
                int c = n0 + wn*32 + tn*8 + tig*2;
                size_t base = (size_t)m * DFF + c;
                float u0 = accU[tm][tn][half*2], u1 = accU[tm][tn][half*2+1];
                float v0 = accV[tm][tn][half*2], v1 = accV[tm][tn][half*2+1];
                float w0 = v0 * u0 / (1.0f + __expf(-u0));
                float w1 = v1 * u1 / (1.0f + __expf(-u1));
                *(uint32_t*)(Cg + base) = f22h(w0, w1);
            }
        }
    }
}

// ---------------- fp16 flash attention (causal) ----------------
#define FA_SMEM (16384 + 3*16384)

__global__ __launch_bounds__(256, 2) void flash_tc(
    const __half* __restrict__ Qg, const __half* __restrict__ Kg,
    const __half* __restrict__ Vg, __half* __restrict__ Og)
{
    extern __shared__ char smem[];
    uint32_t sb = smem_u32(smem);
    const int tid  = threadIdx.x;
    const int lane = tid & 31;
    const int w    = tid >> 5;
    const int gid  = lane >> 2, tig = lane & 3;
    const int qt   = (int)gridDim.x - 1 - (int)blockIdx.x;
    const int bh   = blockIdx.y;
    const int b    = bh >> 4, head = bh & 15;
    const size_t base = (size_t)bh * SEQ * DK;
    const int q0 = qt * 128;
    const int NT = 2 * qt + 2;

    #pragma unroll
    for (int j = 0; j < 4; j++){
        int i = j * 256 + tid;
        int r = i >> 3, c16 = i & 7;
        cpa16(sb + SW128((uint32_t)(r << 7) + (c16 << 4)),
              Qg + base + (size_t)(q0 + r) * DK + c16 * 8);
    }
    cp_commit();

    auto load_kv = [&](int kt, int stage){
        uint32_t tb = sb + 16384 + stage * 16384;
        size_t kb = base + (size_t)kt * 64 * DK;
        #pragma unroll
        for (int j = 0; j < 2; j++){
            int i = j * 256 + tid;
            int r = i >> 3, c16 = i & 7;
            uint32_t o = SW128((uint32_t)(r << 7) + (c16 << 4));
            cpa16(tb + o,        Kg + kb + (size_t)r * DK + c16 * 8);
            cpa16(tb + 8192 + o, Vg + kb + (size_t)r * DK + c16 * 8);
        }
        cp_commit();
    };
    load_kv(0, 0);
    load_kv(1, 1);

    cp_wait2();
    __syncthreads();

    uint32_t qf[4][4];
    #pragma unroll
    for (int s = 0; s < 4; s++){
        uint32_t o = (uint32_t)((w*16 + (lane & 15)) << 7) + s*32 + ((lane >> 4) << 4);
        ldsm4(qf[s], sb + SW128(o));
    }

    float oacc[8][4];
    #pragma unroll
    for (int i = 0; i < 8; i++)
        #pragma unroll
        for (int j = 0; j < 4; j++) oacc[i][j] = 0.0f;
    float m0 = -1e30f, m1 = -1e30f, l0 = 0.0f, l1 = 0.0f;
    const int qrow0 = q0 + w * 16;

    for (int kt = 0; kt < NT; kt++){
        if (kt + 1 < NT) cp_wait1(); else cp_wait0();
        __syncthreads();
        uint32_t tb = sb + 16384 + (kt % 3) * 16384;

        float sc[8][4];
        #pragma unroll
        for (int i = 0; i < 8; i++)
            #pragma unroll
            for (int j = 0; j < 4; j++) sc[i][j] = 0.0f;

        #pragma unroll
        for (int s = 0; s < 4; s++){
            uint32_t kf[4][4];
            #pragma unroll
            for (int g = 0; g < 4; g++){
                uint32_t o = (uint32_t)((g*16 + (lane & 15)) << 7) + s*32 + ((lane >> 4) << 4);
                ldsm4(kf[g], tb + SW128(o));
            }
            #pragma unroll
            for (int g = 0; g < 4; g++)
                #pragma unroll
                for (int j = 0; j < 2; j++)
                    mma16816(sc[g*2+j], qf[s], kf[g][j], kf[g][j+2]);
        }

        if (kt*64 + 63 > qrow0){
            int r0 = qrow0 + gid, r1 = r0 + 8;
            #pragma unroll
            for (int tn = 0; tn < 8; tn++){
                int key = kt*64 + tn*8 + tig*2;
                if (key     > r0) sc[tn][0] = -1e9f;
                if (key + 1 > r0) sc[tn][1] = -1e9f;
                if (key     > r1) sc[tn][2] = -1e9f;
                if (key + 1 > r1) sc[tn][3] = -1e9f;
            }
        }

        float t0 = -1e30f, t1 = -1e30f;
        #pragma unroll
        for (int tn = 0; tn < 8; tn++){
            t0 = fmaxf(t0, fmaxf(sc[tn][0], sc[tn][1]));
            t1 = fmaxf(t1, fmaxf(sc[tn][2], sc[tn][3]));
        }
        t0 = fmaxf(t0, __shfl_xor_sync(0xffffffffu, t0, 1));
        t0 = fmaxf(t0, __shfl_xor_sync(0xffffffffu, t0, 2));
        t1 = fmaxf(t1, __shfl_xor_sync(0xffffffffu, t1, 1));
        t1 = fmaxf(t1, __shfl_xor_sync(0xffffffffu, t1, 2));
        float nm0 = fmaxf(m0, t0), nm1 = fmaxf(m1, t1);
        float c0 = __expf(m0 - nm0), c1 = __expf(m1 - nm1);
        l0 *= c0; l1 *= c1;
        #pragma unroll
        for (int tn = 0; tn < 8; tn++){
            sc[tn][0] = __expf(sc[tn][0] - nm0);
            sc[tn][1] = __expf(sc[tn][1] - nm0);
            sc[tn][2] = __expf(sc[tn][2] - nm1);
            sc[tn][3] = __expf(sc[tn][3] - nm1);
            l0 += sc[tn][0] + sc[tn][1];
            l1 += sc[tn][2] + sc[tn][3];
        }
        #pragma unroll
        for (int od = 0; od < 8; od++){
            oacc[od][0] *= c0; oacc[od][1] *= c0;
            oacc[od][2] *= c1; oacc[od][3] *= c1;
        }
        m0 = nm0; m1 = nm1;

        uint32_t pf[4][4];
        #pragma unroll
        for (int s = 0; s < 4; s++){
            pf[s][0] = f22h(sc[2*s][0],   sc[2*s][1]);
            pf[s][1] = f22h(sc[2*s][2],   sc[2*s][3]);
            pf[s][2] = f22h(sc[2*s+1][0], sc[2*s+1][1]);
            pf[s][3] = f22h(sc[2*s+1][2], sc[2*s+1][3]);
        }

        #pragma unroll
        for (int s = 0; s < 4; s++){
            uint32_t vf[4][4];
            #pragma unroll
            for (int gd = 0; gd < 4; gd++){
                uint32_t row = s*16 + (lane & 7) + ((lane & 16) >> 1);
                uint32_t col = gd*16 + (lane & 8);
                ldsm4t(vf[gd], tb + 8192 + SW128((row << 7) + (col << 1)));
            }
            #pragma unroll
            for (int gd = 0; gd < 4; gd++)
                #pragma unroll
                for (int j = 0; j < 2; j++)
                    mma16816(oacc[gd*2+j], pf[s], vf[gd][j], vf[gd][j+2]);
        }

        if (kt + 2 < NT) load_kv(kt + 2, (kt + 2) % 3);
    }

    l0 += __shfl_xor_sync(0xffffffffu, l0, 1);
    l0 += __shfl_xor_sync(0xffffffffu, l0, 2);
    l1 += __shfl_xor_sync(0xffffffffu, l1, 1);
    l1 += __shfl_xor_sync(0xffffffffu, l1, 2);
    float inv0 = 1.0f / l0, inv1 = 1.0f / l1;

    int q = qrow0 + gid;
    size_t tk0 = (size_t)(b * SEQ + q) * DM + head * 64;
    size_t tk1 = tk0 + (size_t)8 * DM;
    #pragma unroll
    for (int od = 0; od < 8; od++){
        int d = od*8 + tig*2;
        *(uint32_t*)(Og + tk0 + d) = f22h(oacc[od][0] * inv0, oacc[od][1] * inv0);
        *(uint32_t*)(Og + tk1 + d) = f22h(oacc[od][2] * inv1, oacc[od][3] * inv1);
    }
}

// ---------------- launch ----------------
extern "C" void kernel_launch(void* const* d_in, const int* in_sizes, int n_in,
                              void* d_out, int out_size)
{
    const float* x  = (const float*)d_in[0];
    const float* Wq = (const float*)d_in[1];
    const float* Wk = (const float*)d_in[2];
    const float* Wv = (const float*)d_in[3];
    const float* Wo = (const float*)d_in[4];
    const float* g1 = (const float*)d_in[5];
    const float* g2 = (const float*)d_in[6];
    const float* W1 = (const float*)d_in[7];
    const float* W3 = (const float*)d_in[8];
    const float* W2 = (const float*)d_in[9];
    float* out = (float*)d_out;

    float *x1;
    __half *h1,*at,*h2,*gb,*w,*q,*k,*v;
    cudaGetSymbolAddress((void**)&x1, g_x1);
    cudaGetSymbolAddress((void**)&h1, g_h1);
    cudaGetSymbolAddress((void**)&at, g_at);
    cudaGetSymbolAddress((void**)&h2, g_h2);
    cudaGetSymbolAddress((void**)&gb, g_gb);
    cudaGetSymbolAddress((void**)&w,  g_w);
    cudaGetSymbolAddress((void**)&q,  g_q);
    cudaGetSymbolAddress((void**)&k,  g_k);
    cudaGetSymbolAddress((void**)&v,  g_v);

    cudaFuncSetAttribute(gemm_qkv, cudaFuncAttributeMaxDynamicSharedMemorySize, GH_SMEM);
    cudaFuncSetAttribute(gemm_add, cudaFuncAttributeMaxDynamicSharedMemorySize, GH_SMEM);
    cudaFuncSetAttribute(gemm_w13, cudaFuncAttributeMaxDynamicSharedMemorySize, W13_SMEM);
    cudaFuncSetAttribute(flash_tc, cudaFuncAttributeMaxDynamicSharedMemorySize, FA_SMEM);

    prep_k<<<6400, 256>>>(x, g1, Wq, Wk, Wv, Wo, W1, W3, W2, w, h1);

    gemm_qkv<<<dim3(3*DM/64, TOKENS/128), 256, GH_SMEM>>>(h1, w, q, k, v);

    flash_tc<<<dim3(SEQ / 128, 2 * NH), 256, FA_SMEM>>>(q, k, v, at);

    gemm_add<<<dim3(DM/64, TOKENS/128), 256, GH_SMEM>>>(at, w + WOFF_O, x1, x, DM, DM);
    rms_h_k<<<TOKENS, 256>>>(x1, g2, h2);

    gemm_w13<<<dim3(DFF/64, TOKENS/128), 256, W13_SMEM>>>(h2, w + WOFF_1, w + WOFF_3, gb);
    gemm_add<<<dim3(DM/64, TOKENS/128), 256, GH_SMEM>>>(gb, w + WOFF_2, out, x1, DM, DFF);
}

// round 17
// speedup vs baseline: 1.0710x; 1.0214x over previous
#include <cuda_runtime.h>
#include <cuda_fp16.h>
#include <math.h>
#include <stdint.h>

#define TOKENS 4096
#define DM     1024
#define DFF    4096
#define SEQ    2048
#define NH     16
#define DK     64

// ---------------- scratch ----------------
__device__ float g_x1[TOKENS*DM];
__device__ float g_cs[SEQ*32];
__device__ float g_sn[SEQ*32];

__device__ __half g_h1[TOKENS*DM];
__device__ __half g_at[TOKENS*DM];
__device__ __half g_h2[TOKENS*DM];
__device__ __half g_gb[TOKENS*DFF];
__device__ __half g_q[TOKENS*DM];
__device__ __half g_k[TOKENS*DM];
__device__ __half g_v[TOKENS*DM];

#define WOFF_Q  0
#define WOFF_K  (1u<<20)
#define WOFF_V  (2u<<20)
#define WOFF_O  (3u<<20)
#define WOFF_1  (4u<<20)
#define WOFF_3  (8u<<20)
#define WOFF_2  (12u<<20)
__device__ __half g_w[16u<<20];

// ---------------- helpers ----------------
__device__ __forceinline__ uint32_t smem_u32(const void* p){
    uint32_t r;
    asm("{ .reg .u64 t; cvta.to.shared.u64 t, %1; cvt.u32.u64 %0, t; }" : "=r"(r) : "l"(p));
    return r;
}
__device__ __forceinline__ void cpa16(uint32_t dst, const void* src){
    asm volatile("cp.async.cg.shared.global [%0], [%1], 16;" :: "r"(dst), "l"(src) : "memory");
}
__device__ __forceinline__ void cp_commit(){ asm volatile("cp.async.commit_group;" ::: "memory"); }
__device__ __forceinline__ void cp_wait2(){ asm volatile("cp.async.wait_group 2;" ::: "memory"); }
__device__ __forceinline__ void cp_wait1(){ asm volatile("cp.async.wait_group 1;" ::: "memory"); }
__device__ __forceinline__ void cp_wait0(){ asm volatile("cp.async.wait_group 0;" ::: "memory"); }

__device__ __forceinline__ void ldsm4(uint32_t* r, uint32_t addr){
    asm volatile("ldmatrix.sync.aligned.m8n8.x4.shared.b16 {%0,%1,%2,%3}, [%4];"
        : "=r"(r[0]),"=r"(r[1]),"=r"(r[2]),"=r"(r[3]) : "r"(addr));
}
__device__ __forceinline__ void ldsm4t(uint32_t* r, uint32_t addr){
    asm volatile("ldmatrix.sync.aligned.m8n8.x4.trans.shared.b16 {%0,%1,%2,%3}, [%4];"
        : "=r"(r[0]),"=r"(r[1]),"=r"(r[2]),"=r"(r[3]) : "r"(addr));
}
__device__ __forceinline__ void mma16816(float* c, const uint32_t* a, uint32_t b0, uint32_t b1){
    asm volatile("mma.sync.aligned.m16n8k16.row.col.f32.f16.f16.f32 "
        "{%0,%1,%2,%3}, {%4,%5,%6,%7}, {%8,%9}, {%0,%1,%2,%3};"
        : "+f"(c[0]),"+f"(c[1]),"+f"(c[2]),"+f"(c[3])
        : "r"(a[0]),"r"(a[1]),"r"(a[2]),"r"(a[3]), "r"(b0),"r"(b1));
}
#define SW128(o) ((o) ^ (((o)>>3)&0x70))

__device__ __forceinline__ uint32_t f22h(float x, float y){
    __half2 h = __floats2half2_rn(x, y);
    return *reinterpret_cast<uint32_t*>(&h);
}

// ---------------- merged preamble: rope table + weight cvt + rmsnorm1 ----------------
// blocks [0,256): rope | [256,2304): cvt (8 float4/thread) | [2304,6400): rms1
__global__ __launch_bounds__(256) void prep_k(
    const float* __restrict__ x,  const float* __restrict__ g1,
    const float* __restrict__ Wq, const float* __restrict__ Wk,
    const float* __restrict__ Wv, const float* __restrict__ Wo,
    const float* __restrict__ W1, const float* __restrict__ W3,
    const float* __restrict__ W2,
    __half* __restrict__ w, __half* __restrict__ h1out)
{
    int blk = blockIdx.x;
    int t   = threadIdx.x;
    if (blk < 256){
        __shared__ float invf[32];
        if (t < 32) invf[t] = (float)pow(10000.0, -(double)(2 * t) / 64.0);
        __syncthreads();
        int i = blk * 256 + t;
        int pos = i >> 5;
        int j   = i & 31;
        float ang = (float)pos * invf[j];
        g_cs[i] = cosf(ang);
        g_sn[i] = sinf(ang);
    } else if (blk < 2304){
        int gb = blk - 256;
        const float* src; uint32_t woff; int lb;
        if (gb < 512){
            int m = gb >> 7; lb = gb & 127;
            src = (m==0)?Wq:(m==1)?Wk:(m==2)?Wv:Wo;
            woff = (uint32_t)m << 20;
        } else if (gb < 1024){ src = W1; woff = WOFF_1; lb = gb - 512; }
        else if (gb < 1536){ src = W3; woff = WOFF_3; lb = gb - 1024; }
        else               { src = W2; woff = WOFF_2; lb = gb - 1536; }
        const float4* sp = (const float4*)src;
        float4 v[8];
        #pragma unroll
        for (int j = 0; j < 8; j++)
            v[j] = __ldcs(&sp[lb * 2048 + j * 256 + t]);
        uint2* hp = (uint2*)(w + woff);
        #pragma unroll
        for (int j = 0; j < 8; j++){
            int i4 = lb * 2048 + j * 256 + t;
            hp[i4] = make_uint2(f22h(v[j].x, v[j].y), f22h(v[j].z, v[j].w));
        }
    } else {
        int row = blk - 2304;
        const float4* xr = (const float4*)(x + (size_t)row * DM);
        float4 xv = xr[t];
        float ss = xv.x*xv.x + xv.y*xv.y + xv.z*xv.z + xv.w*xv.w;
        #pragma unroll
        for (int off = 16; off > 0; off >>= 1)
            ss += __shfl_xor_sync(0xffffffffu, ss, off);
        __shared__ float warpsum[8];
        if ((t & 31) == 0) warpsum[t >> 5] = ss;
        __syncthreads();
        float tot = warpsum[0]+warpsum[1]+warpsum[2]+warpsum[3]
                  + warpsum[4]+warpsum[5]+warpsum[6]+warpsum[7];
        float r = rsqrtf(tot * (1.0f / (float)DM) + 1e-5f);
        float4 gv = ((const float4*)g1)[t];
        size_t base4 = (size_t)row * (DM/4) + t;
        ((uint2*)h1out)[base4] = make_uint2(f22h(xv.x*r*gv.x, xv.y*r*gv.y),
                                            f22h(xv.z*r*gv.z, xv.w*r*gv.w));
    }
}

// ---------------- RMSNorm -> fp16 (second norm) ----------------
__global__ __launch_bounds__(256) void rms_h_k(const float* __restrict__ x,
                                               const float* __restrict__ g,
                                               __half* __restrict__ o) {
    int row = blockIdx.x;
    int t   = threadIdx.x;
    const float4* xr = (const float4*)(x + (size_t)row * DM);
    float4 xv = xr[t];
    float ss = xv.x*xv.x + xv.y*xv.y + xv.z*xv.z + xv.w*xv.w;
    #pragma unroll
    for (int off = 16; off > 0; off >>= 1)
        ss += __shfl_xor_sync(0xffffffffu, ss, off);
    __shared__ float warpsum[8];
    if ((t & 31) == 0) warpsum[t >> 5] = ss;
    __syncthreads();
    float tot = warpsum[0]+warpsum[1]+warpsum[2]+warpsum[3]
              + warpsum[4]+warpsum[5]+warpsum[6]+warpsum[7];
    float r = rsqrtf(tot * (1.0f / (float)DM) + 1e-5f);
    float4 gv = ((const float4*)g)[t];
    size_t base4 = (size_t)row * (DM/4) + t;
    ((uint2*)o)[base4] = make_uint2(f22h(xv.x*r*gv.x, xv.y*r*gv.y),
                                    f22h(xv.z*r*gv.z, xv.w*r*gv.w));
}

// =====================================================================
// fp16 GEMM engine: CTA 128x64, 256 thr (2 CTAs/SM), warp 4x2 of 32x32,
// BK=64, SW128 128B rows, 4-stage. Stage (24 KB): A@0(16K) B@16K(8K).
// =====================================================================
#define STGH     24576
#define GH_SMEM  (4*STGH)

__device__ __forceinline__ void gh_load(
    uint32_t tb, int tid, int m0, int n0, int kc, int K,
    const __half* A, const __half* B)
{
    int k0 = kc * 64;
    #pragma unroll
    for (int j = 0; j < 4; j++){
        int i = j * 256 + tid;
        int r = i >> 3, c16 = i & 7;
        cpa16(tb + SW128((uint32_t)(r << 7) + (c16 << 4)),
              A + (size_t)(m0 + r) * K + k0 + c16 * 8);
    }
    #pragma unroll
    for (int j = 0; j < 2; j++){
        int i = j * 256 + tid;
        int r = i >> 3, c16 = i & 7;
        cpa16(tb + 16384 + SW128((uint32_t)(r << 7) + (c16 << 4)),
              B + (size_t)(n0 + r) * K + k0 + c16 * 8);
    }
    cp_commit();
}

struct FragsH { uint32_t a[2][4], b[2][4]; };

__device__ __forceinline__ void gh_ldfrag(FragsH& f, uint32_t tb, int lane, int wm, int wn, int s){
    uint32_t colb = (uint32_t)(s*32) + ((lane >> 4) << 4);
    #pragma unroll
    for (int t = 0; t < 2; t++)
        ldsm4(f.a[t], tb + SW128((uint32_t)((wm*32 + t*16 + (lane & 15)) << 7) + colb));
    #pragma unroll
    for (int g = 0; g < 2; g++)
        ldsm4(f.b[g], tb + 16384 + SW128((uint32_t)((wn*32 + g*16 + (lane & 15)) << 7) + colb));
}

__device__ __forceinline__ void gh_mma(float acc[2][4][4], const FragsH& f){
    #pragma unroll
    for (int t = 0; t < 2; t++)
        #pragma unroll
        for (int g = 0; g < 2; g++)
            #pragma unroll
            for (int j = 0; j < 2; j++)
                mma16816(acc[t][g*2+j], f.a[t], f.b[g][j], f.b[g][j+2]);
}

__device__ __forceinline__ void gh_chunk(uint32_t tb, int lane, int wm, int wn, float acc[2][4][4]){
    FragsH f0, f1;
    gh_ldfrag(f0, tb, lane, wm, wn, 0);
    gh_ldfrag(f1, tb, lane, wm, wn, 1);
    gh_mma(acc, f0);
    gh_ldfrag(f0, tb, lane, wm, wn, 2);
    gh_mma(acc, f1);
    gh_ldfrag(f1, tb, lane, wm, wn, 3);
    gh_mma(acc, f0);
    gh_mma(acc, f1);
}

#define GH_MAIN(A_, B_, KDIM)                                                 \
    gh_load(sb, tid, m0, n0, 0, KDIM, A_, B_);                                \
    gh_load(sb + STGH, tid, m0, n0, 1, KDIM, A_, B_);                         \
    gh_load(sb + 2*STGH, tid, m0, n0, 2, KDIM, A_, B_);                       \
    for (int kc = 0; kc < NC; kc++){                                          \
        if (kc + 2 < NC) cp_wait2();                                          \
        else if (kc + 1 < NC) cp_wait1();                                     \
        else cp_wait0();                                                      \
        __syncthreads();                                                      \
        if (kc + 3 < NC)                                                      \
            gh_load(sb + ((kc+3)&3)*STGH, tid, m0, n0, kc+3, KDIM, A_, B_);   \
        gh_chunk(sb + (kc&3)*STGH, lane, wm, wn, acc);                        \
    }

// ---------------- fused QKV GEMM (N=3072) ----------------
__global__ __launch_bounds__(256, 2) void gemm_qkv(
    const __half* __restrict__ A, const __half* __restrict__ B,
    __half* __restrict__ Q, __half* __restrict__ K_, __half* __restrict__ V)
{
    extern __shared__ char smem[];
    uint32_t sb = smem_u32(smem);
    const int tid  = threadIdx.x;
    const int lane = tid & 31;
    const int wid  = tid >> 5;
    const int wm   = wid & 3;
    const int wn   = wid >> 2;
    const int m0 = blockIdx.y * 128, n0 = blockIdx.x * 64;
    const int NC = DM / 64;

    float acc[2][4][4];
    #pragma unroll
    for (int i = 0; i < 2; i++)
        #pragma unroll
        for (int j = 0; j < 4; j++)
            #pragma unroll
            for (int kk = 0; kk < 4; kk++) acc[i][j][kk] = 0.0f;

    GH_MAIN(A, B, DM)

    const int mtx = n0 >> 10;
    const float scl = (mtx == 0) ? 0.125f : 1.0f;
    __half* D = (mtx==0)?Q:(mtx==1)?K_:V;
    const int gid = lane >> 2, tig = lane & 3;
    #pragma unroll
    for (int tm = 0; tm < 2; tm++){
        #pragma unroll
        for (int half = 0; half < 2; half++){
            int m = m0 + wm*32 + tm*16 + gid + half*8;
            int pos = m & (SEQ - 1), b = m >> 11;
            #pragma unroll
            for (int tn = 0; tn < 4; tn++){
                int cc = (n0 & 1023) + wn*32 + tn*8 + tig*2;
                int head = cc >> 6, hi = cc & 63;
                size_t ob = ((size_t)(b * NH + head) * SEQ + pos) * DK + hi;
                float v0 = acc[tm][tn][half*2];
                float v1 = acc[tm][tn][half*2 + 1];
                float w0, w1;
                if (mtx < 2){
                    float cs = g_cs[pos * 32 + (hi >> 1)];
                    float sn = g_sn[pos * 32 + (hi >> 1)];
                    w0 = (v0 * cs - v1 * sn) * scl;
                    w1 = (v0 * sn + v1 * cs) * scl;
                } else { w0 = v0; w1 = v1; }
                *(uint32_t*)(D + ob) = f22h(w0, w1);
            }
        }
    }
}

// ---------------- GEMM + residual add (Wo, W2) ----------------
__global__ __launch_bounds__(256, 2) void gemm_add(
    const __half* __restrict__ A, const __half* __restrict__ B,
    float* __restrict__ C, const float* __restrict__ other, int N, int K)
{
    extern __shared__ char smem[];
    uint32_t sb = smem_u32(smem);
    const int tid  = threadIdx.x;
    const int lane = tid & 31;
    const int wid  = tid >> 5;
    const int wm   = wid & 3;
    const int wn   = wid >> 2;
    const int m0 = blockIdx.y * 128, n0 = blockIdx.x * 64;
    const int NC = K / 64;

    float acc[2][4][4];
    #pragma unroll
    for (int i = 0; i < 2; i++)
        #pragma unroll
        for (int j = 0; j < 4; j++)
            #pragma unroll
            for (int kk = 0; kk < 4; kk++) acc[i][j][kk] = 0.0f;

    GH_MAIN(A, B, K)

    const int gid = lane >> 2, tig = lane & 3;
    #pragma unroll
    for (int tm = 0; tm < 2; tm++){
        #pragma unroll
        for (int half = 0; half < 2; half++){
            int m = m0 + wm*32 + tm*16 + gid + half*8;
            #pragma unroll
            for (int tn = 0; tn < 4; tn++){
                int c = n0 + wn*32 + tn*8 + tig*2;
                size_t base = (size_t)m * N + c;
                float2 o2 = *(const float2*)(other + base);
                float2 r2 = make_float2(o2.x + acc[tm][tn][half*2],
                                        o2.y + acc[tm][tn][half*2 + 1]);
                *(float2*)(C + base) = r2;
            }
        }
    }
}

// ---------------- fused W1/W3 GEMM + silu(u)*v -> fp16 (3-stage) ----------------
#define W13_STG   32768
#define W13_SMEM  (3*W13_STG)

__global__ __launch_bounds__(256, 2) void gemm_w13(
    const __half* __restrict__ A,
    const __half* __restrict__ B1, const __half* __restrict__ B3,
    __half* __restrict__ Cg)
{
    extern __shared__ char smem[];
    uint32_t sb = smem_u32(smem);
    const int tid  = threadIdx.x;
    const int lane = tid & 31;
    const int wid  = tid >> 5;
    const int wm   = wid & 3;
    const int wn   = wid >> 2;
    const int m0 = blockIdx.y * 128, n0 = blockIdx.x * 64;
    const int NC = DM / 64;
    const int K  = DM;

    float accU[2][4][4], accV[2][4][4];
    #pragma unroll
    for (int i = 0; i < 2; i++)
        #pragma unroll
        for (int j = 0; j < 4; j++)
            #pragma unroll
            for (int kk = 0; kk < 4; kk++){ accU[i][j][kk] = 0.0f; accV[i][j][kk] = 0.0f; }

    auto load_chunk = [&](int kc, int stage){
        uint32_t tb = sb + stage * W13_STG;
        int k0 = kc * 64;
        #pragma unroll
        for (int j = 0; j < 4; j++){
            int i = j * 256 + tid;
            int r = i >> 3, c16 = i & 7;
            cpa16(tb + SW128((uint32_t)(r << 7) + (c16 << 4)),
                  A + (size_t)(m0 + r) * K + k0 + c16 * 8);
        }
        #pragma unroll
        for (int j = 0; j < 2; j++){
            int i = j * 256 + tid;
            int r = i >> 3, c16 = i & 7;
            uint32_t o = SW128((uint32_t)(r << 7) + (c16 << 4));
            cpa16(tb + 16384 + o, B1 + (size_t)(n0 + r) * K + k0 + c16 * 8);
            cpa16(tb + 24576 + o, B3 + (size_t)(n0 + r) * K + k0 + c16 * 8);
        }
        cp_commit();
    };

    load_chunk(0, 0);
    load_chunk(1, 1);

    for (int kc = 0; kc < NC; kc++){
        if (kc + 1 < NC) cp_wait1(); else cp_wait0();
        __syncthreads();
        if (kc + 2 < NC) load_chunk(kc + 2, (kc + 2) % 3);
        uint32_t tb = sb + (kc % 3) * W13_STG;

        #pragma unroll
        for (int s = 0; s < 4; s++){
            uint32_t colb = (uint32_t)(s*32) + ((lane >> 4) << 4);
            uint32_t a[2][4], b1[2][4], b3[2][4];
            #pragma unroll
            for (int t = 0; t < 2; t++)
                ldsm4(a[t], tb + SW128((uint32_t)((wm*32 + t*16 + (lane & 15)) << 7) + colb));
            #pragma unroll
            for (int g = 0; g < 2; g++){
                uint32_t so = SW128((uint32_t)((wn*32 + g*16 + (lane & 15)) << 7) + colb);
                ldsm4(b1[g], tb + 16384 + so);
                ldsm4(b3[g], tb + 24576 + so);
            }
            #pragma unroll
            for (int t = 0; t < 2; t++)
                #pragma unroll
                for (int g = 0; g < 2; g++)
                    #pragma unroll
                    for (int j = 0; j < 2; j++){
                        mma16816(accU[t][g*2+j], a[t], b1[g][j], b1[g][j+2]);
                        mma16816(accV[t][g*2+j], a[t], b3[g][j], b3[g][j+2]);
                    }
        }
    }

    const int gid = lane >> 2, tig = lane & 3;
    #pragma unroll
    for (int tm = 0; tm < 2; tm++){
        #pragma unroll
        for (int half = 0; half < 2; half++){
            int m = m0 + wm*32 + tm*16 + gid + half*8;
            #pragma unroll
            for (int tn = 0; tn < 4; tn++){
                int c = n0 + wn*32 + tn*8 + tig*2;
                size_t base = (size_t)m * DFF + c;
                float u0 = accU[tm][tn][half*2], u1 = accU[tm][tn][half*2+1];
                float v0 = accV[tm][tn][half*2], v1 = accV[tm][tn][half*2+1];
                float w0 = v0 * u0 / (1.0f + __expf(-u0));
                float w1 = v1 * u1 / (1.0f + __expf(-u1));
                *(uint32_t*)(Cg + base) = f22h(w0, w1);
            }
        }
    }
}

// ---------------- fp16 flash attention (causal), 4 warps x 32 q-rows ----------------
// smem: Q 16K @0; KV stages @16K: [K 8K | V 8K] x3 = 64 KB total
#define FA_SMEM (16384 + 3*16384)

__global__ __launch_bounds__(128, 2) void flash_tc(
    const __half* __restrict__ Qg, const __half* __restrict__ Kg,
    const __half* __restrict__ Vg, __half* __restrict__ Og)
{
    extern __shared__ char smem[];
    uint32_t sb = smem_u32(smem);
    const int tid  = threadIdx.x;
    const int lane = tid & 31;
    const int w    = tid >> 5;          // 0..3
    const int gid  = lane >> 2, tig = lane & 3;
    const int qt   = (int)gridDim.x - 1 - (int)blockIdx.x;
    const int bh   = blockIdx.y;
    const int b    = bh >> 4, head = bh & 15;
    const size_t base = (size_t)bh * SEQ * DK;
    const int q0 = qt * 128;
    const int NT = 2 * qt + 2;

    // Q: 1024 16B-chunks over 128 thr
    #pragma unroll
    for (int j = 0; j < 8; j++){
        int i = j * 128 + tid;
        int r = i >> 3, c16 = i & 7;
        cpa16(sb + SW128((uint32_t)(r << 7) + (c16 << 4)),
              Qg + base + (size_t)(q0 + r) * DK + c16 * 8);
    }
    cp_commit();

    auto load_kv = [&](int kt, int stage){
        uint32_t tb = sb + 16384 + stage * 16384;
        size_t kb = base + (size_t)kt * 64 * DK;
        #pragma unroll
        for (int j = 0; j < 4; j++){
            int i = j * 128 + tid;
            int r = i >> 3, c16 = i & 7;
            uint32_t o = SW128((uint32_t)(r << 7) + (c16 << 4));
            cpa16(tb + o,        Kg + kb + (size_t)r * DK + c16 * 8);
            cpa16(tb + 8192 + o, Vg + kb + (size_t)r * DK + c16 * 8);
        }
        cp_commit();
    };
    load_kv(0, 0);
    load_kv(1, 1);

    cp_wait2();
    __syncthreads();

    // Q fragments: 2 row-tiles of 16 per warp
    uint32_t qf[2][4][4];
    #pragma unroll
    for (int rt = 0; rt < 2; rt++)
        #pragma unroll
        for (int s = 0; s < 4; s++){
            uint32_t o = (uint32_t)((w*32 + rt*16 + (lane & 15)) << 7) + s*32 + ((lane >> 4) << 4);
            ldsm4(qf[rt][s], sb + SW128(o));
        }

    float oacc[2][8][4];
    #pragma unroll
    for (int rt = 0; rt < 2; rt++)
        #pragma unroll
        for (int i = 0; i < 8; i++)
            #pragma unroll
            for (int j = 0; j < 4; j++) oacc[rt][i][j] = 0.0f;
    float mm[2][2], ll[2][2];
    #pragma unroll
    for (int rt = 0; rt < 2; rt++){ mm[rt][0] = -1e30f; mm[rt][1] = -1e30f; ll[rt][0] = 0.0f; ll[rt][1] = 0.0f; }
    const int qrow0 = q0 + w * 32;

    for (int kt = 0; kt < NT; kt++){
        if (kt + 1 < NT) cp_wait1(); else cp_wait0();
        __syncthreads();
        uint32_t tb = sb + 16384 + (kt % 3) * 16384;

        float sc[2][8][4];
        #pragma unroll
        for (int rt = 0; rt < 2; rt++)
            #pragma unroll
            for (int i = 0; i < 8; i++)
                #pragma unroll
                for (int j = 0; j < 4; j++) sc[rt][i][j] = 0.0f;

        #pragma unroll
        for (int s = 0; s < 4; s++){
            uint32_t kf[4][4];
            #pragma unroll
            for (int g = 0; g < 4; g++){
                uint32_t o = (uint32_t)((g*16 + (lane & 15)) << 7) + s*32 + ((lane >> 4) << 4);
                ldsm4(kf[g], tb + SW128(o));
            }
            #pragma unroll
            for (int rt = 0; rt < 2; rt++)
                #pragma unroll
                for (int g = 0; g < 4; g++)
                    #pragma unroll
                    for (int j = 0; j < 2; j++)
                        mma16816(sc[rt][g*2+j], qf[rt][s], kf[g][j], kf[g][j+2]);
        }

        if (kt*64 + 63 > qrow0){
            #pragma unroll
            for (int rt = 0; rt < 2; rt++){
                int r0 = qrow0 + rt*16 + gid, r1 = r0 + 8;
                #pragma unroll
                for (int tn = 0; tn < 8; tn++){
                    int key = kt*64 + tn*8 + tig*2;
                    if (key     > r0) sc[rt][tn][0] = -1e9f;
                    if (key + 1 > r0) sc[rt][tn][1] = -1e9f;
                    if (key     > r1) sc[rt][tn][2] = -1e9f;
                    if (key + 1 > r1) sc[rt][tn][3] = -1e9f;
                }
            }
        }

        uint32_t pf[2][4][4];
        #pragma unroll
        for (int rt = 0; rt < 2; rt++){
            float t0 = -1e30f, t1 = -1e30f;
            #pragma unroll
            for (int tn = 0; tn < 8; tn++){
                t0 = fmaxf(t0, fmaxf(sc[rt][tn][0], sc[rt][tn][1]));
                t1 = fmaxf(t1, fmaxf(sc[rt][tn][2], sc[rt][tn][3]));
            }
            t0 = fmaxf(t0, __shfl_xor_sync(0xffffffffu, t0, 1));
            t0 = fmaxf(t0, __shfl_xor_sync(0xffffffffu, t0, 2));
            t1 = fmaxf(t1, __shfl_xor_sync(0xffffffffu, t1, 1));
            t1 = fmaxf(t1, __shfl_xor_sync(0xffffffffu, t1, 2));
            float nm0 = fmaxf(mm[rt][0], t0), nm1 = fmaxf(mm[rt][1], t1);
            float c0 = __expf(mm[rt][0] - nm0), c1 = __expf(mm[rt][1] - nm1);
            ll[rt][0] *= c0; ll[rt][1] *= c1;
            #pragma unroll
            for (int tn = 0; tn < 8; tn++){
                sc[rt][tn][0] = __expf(sc[rt][tn][0] - nm0);
                sc[rt][tn][1] = __expf(sc[rt][tn][1] - nm0);
                sc[rt][tn][2] = __expf(sc[rt][tn][2] - nm1);
                sc[rt][tn][3] = __expf(sc[rt][tn][3] - nm1);
                ll[rt][0] += sc[rt][tn][0] + sc[rt][tn][1];
                ll[rt][1] += sc[rt][tn][2] + sc[rt][tn][3];
            }
            #pragma unroll
            for (int od = 0; od < 8; od++){
                oacc[rt][od][0] *= c0; oacc[rt][od][1] *= c0;
                oacc[rt][od][2] *= c1; oacc[rt][od][3] *= c1;
            }
            mm[rt][0] = nm0; mm[rt][1] = nm1;
            #pragma unroll
            for (int s = 0; s < 4; s++){
                pf[rt][s][0] = f22h(sc[rt][2*s][0],   sc[rt][2*s][1]);
                pf[rt][s][1] = f22h(sc[rt][2*s][2],   sc[rt][2*s][3]);
                pf[rt][s][2] = f22h(sc[rt][2*s+1][0], sc[rt][2*s+1][1]);
                pf[rt][s][3] = f22h(sc[rt][2*s+1][2], sc[rt][2*s+1][3]);
            }
        }

        #pragma unroll
        for (int s = 0; s < 4; s++){
            uint32_t vf[4][4];
            #pragma unroll
            for (int gd = 0; gd < 4; gd++){
                uint32_t row = s*16 + (lane & 7) + ((lane & 16) >> 1);
                uint32_t col = gd*16 + (lane & 8);
                ldsm4t(vf[gd], tb + 8192 + SW128((row << 7) + (col << 1)));
            }
            #pragma unroll
            for (int rt = 0; rt < 2; rt++)
                #pragma unroll
                for (int gd = 0; gd < 4; gd++)
                    #pragma unroll
                    for (int j = 0; j < 2; j++)
                        mma16816(oacc[rt][gd*2+j], pf[rt][s], vf[gd][j], vf[gd][j+2]);
        }

        if (kt + 2 < NT) load_kv(kt + 2, (kt + 2) % 3);
    }

    #pragma unroll
    for (int rt = 0; rt < 2; rt++){
        float l0 = ll[rt][0], l1 = ll[rt][1];
        l0 += __shfl_xor_sync(0xffffffffu, l0, 1);
        l0 += __shfl_xor_sync(0xffffffffu, l0, 2);
        l1 += __shfl_xor_sync(0xffffffffu, l1, 1);
        l1 += __shfl_xor_sync(0xffffffffu, l1, 2);
        float inv0 = 1.0f / l0, inv1 = 1.0f / l1;

        int q = qrow0 + rt*16 + gid;
        size_t tk0 = (size_t)(b * SEQ + q) * DM + head * 64;
        size_t tk1 = tk0 + (size_t)8 * DM;
        #pragma unroll
        for (int od = 0; od < 8; od++){
            int d = od*8 + tig*2;
            *(uint32_t*)(Og + tk0 + d) = f22h(oacc[rt][od][0] * inv0, oacc[rt][od][1] * inv0);
            *(uint32_t*)(Og + tk1 + d) = f22h(oacc[rt][od][2] * inv1, oacc[rt][od][3] * inv1);
        }
    }
}

// ---------------- launch ----------------
extern "C" void kernel_launch(void* const* d_in, const int* in_sizes, int n_in,
                              void* d_out, int out_size)
{
    const float* x  = (const float*)d_in[0];
    const float* Wq = (const float*)d_in[1];
    const float* Wk = (const float*)d_in[2];
    const float* Wv = (const float*)d_in[3];
    const float* Wo = (const float*)d_in[4];
    const float* g1 = (const float*)d_in[5];
    const float* g2 = (const float*)d_in[6];
    const float* W1 = (const float*)d_in[7];
    const float* W3 = (const float*)d_in[8];
    const float* W2 = (const float*)d_in[9];
    float* out = (float*)d_out;

    float *x1;
    __half *h1,*at,*h2,*gb,*w,*q,*k,*v;
    cudaGetSymbolAddress((void**)&x1, g_x1);
    cudaGetSymbolAddress((void**)&h1, g_h1);
    cudaGetSymbolAddress((void**)&at, g_at);
    cudaGetSymbolAddress((void**)&h2, g_h2);
    cudaGetSymbolAddress((void**)&gb, g_gb);
    cudaGetSymbolAddress((void**)&w,  g_w);
    cudaGetSymbolAddress((void**)&q,  g_q);
    cudaGetSymbolAddress((void**)&k,  g_k);
    cudaGetSymbolAddress((void**)&v,  g_v);

    cudaFuncSetAttribute(gemm_qkv, cudaFuncAttributeMaxDynamicSharedMemorySize, GH_SMEM);
    cudaFuncSetAttribute(gemm_add, cudaFuncAttributeMaxDynamicSharedMemorySize, GH_SMEM);
    cudaFuncSetAttribute(gemm_w13, cudaFuncAttributeMaxDynamicSharedMemorySize, W13_SMEM);
    cudaFuncSetAttribute(flash_tc, cudaFuncAttributeMaxDynamicSharedMemorySize, FA_SMEM);

    prep_k<<<6400, 256>>>(x, g1, Wq, Wk, Wv, Wo, W1, W3, W2, w, h1);

    gemm_qkv<<<dim3(3*DM/64, TOKENS/128), 256, GH_SMEM>>>(h1, w, q, k, v);

    flash_tc<<<dim3(SEQ / 128, 2 * NH), 128, FA_SMEM>>>(q, k, v, at);

    gemm_add<<<dim3(DM/64, TOKENS/128), 256, GH_SMEM>>>(at, w + WOFF_O, x1, x, DM, DM);
    rms_h_k<<<TOKENS, 256>>>(x1, g2, h2);

    gemm_w13<<<dim3(DFF/64, TOKENS/128), 256, W13_SMEM>>>(h2, w + WOFF_1, w + WOFF_3, gb);
    gemm_add<<<dim3(DM/64, TOKENS/128), 256, GH_SMEM>>>(gb, w + WOFF_2, out, x1, DM, DFF);
}